// round 1
// baseline (speedup 1.0000x reference)
#include <cuda_runtime.h>

#define Bsz 2048
#define Lsz 64
#define Esz 128
#define Hsz 128
#define NSTEPS 126
#define BM 14
#define NT 512
#define GRID 147               // ceil(2048/14)
#define WQS 132                // padded smem row stride (floats) for Wq matrices
#define NEGV -1000000000.0f

// scratch: precomputed e_g[b][l][h], e_p[b][l][h]  (64MB each, module-static: allowed)
__device__ float d_eg[(size_t)Bsz * Lsz * Hsz];
__device__ float d_ep[(size_t)Bsz * Lsz * Hsz];

__device__ __forceinline__ float ftanh(float x) {
    // exact at +/-inf: e=inf -> 1 ; e=0 -> -1. rel err ~1e-6 (EX2 + RCP)
    float e = __expf(2.f * x);
    return 1.f - __fdividef(2.f, e + 1.f);
}
__device__ __forceinline__ float fsigm(float x) {
    return __fdividef(1.f, 1.f + __expf(-x));
}

// ---------------------------------------------------------------------------
// Precompute e_g/e_p: e[b][l][o] = sum_h Wref[o][h]*context[l][b][h] + bref[o]
// grid = 2048 (one block per batch), 128 threads (one per output unit o)
// ---------------------------------------------------------------------------
__global__ void __launch_bounds__(128) ptrnet_pre(
    const float* __restrict__ ctx,                          // (L,B,H)
    const float* __restrict__ gWref, const float* __restrict__ gbref,
    const float* __restrict__ pWref, const float* __restrict__ pbref)
{
    __shared__ float cs[Lsz * Hsz];   // 32KB: context rows for this batch
    const int b = blockIdx.x, t = threadIdx.x;
    for (int l = 0; l < Lsz; l++)
        cs[l * Hsz + t] = ctx[((size_t)l * Bsz + b) * Hsz + t];
    __syncthreads();

    {   // e_g
        float acc[Lsz];
        #pragma unroll
        for (int l = 0; l < Lsz; l++) acc[l] = 0.f;
        const float4* wr = reinterpret_cast<const float4*>(gWref + t * Hsz);
        #pragma unroll 1
        for (int k4 = 0; k4 < 32; k4++) {
            float4 w = wr[k4];
            #pragma unroll
            for (int l = 0; l < Lsz; l++) {
                float4 c = *reinterpret_cast<const float4*>(&cs[l * Hsz + k4 * 4]);
                acc[l] += w.x * c.x + w.y * c.y + w.z * c.z + w.w * c.w;
            }
        }
        float bias = gbref[t];
        #pragma unroll
        for (int l = 0; l < Lsz; l++)
            d_eg[((size_t)b * Lsz + l) * Hsz + t] = acc[l] + bias;
    }
    {   // e_p
        float acc[Lsz];
        #pragma unroll
        for (int l = 0; l < Lsz; l++) acc[l] = 0.f;
        const float4* wr = reinterpret_cast<const float4*>(pWref + t * Hsz);
        #pragma unroll 1
        for (int k4 = 0; k4 < 32; k4++) {
            float4 w = wr[k4];
            #pragma unroll
            for (int l = 0; l < Lsz; l++) {
                float4 c = *reinterpret_cast<const float4*>(&cs[l * Hsz + k4 * 4]);
                acc[l] += w.x * c.x + w.y * c.y + w.z * c.z + w.w * c.w;
            }
        }
        float bias = pbref[t];
        #pragma unroll
        for (int l = 0; l < Lsz; l++)
            d_ep[((size_t)b * Lsz + l) * Hsz + t] = acc[l] + bias;
    }
}

// ---------------------------------------------------------------------------
// Persistent decode kernel: each block owns BM=14 batch rows, runs all steps.
// smem float layout offsets:
// ---------------------------------------------------------------------------
#define OWQG 0                     // g_Wq padded: 128*132         = 16896
#define OWQP 16896                 // p_Wq padded                  = 16896
#define OXH  33792                 // [BM][256]  x | h             = 3584
#define OG   37376                 // [BM][512]  gates             = 7168
#define OC   44544                 // [BM][128]  cell state        = 1792
#define OQ   46336                 // [BM][128]  qg / qp           = 1792
#define OGL  48128                 // [BM][128]  glimpse g_l       = 1792
#define OU   49920                 // [BM][64]   ug / up           = 896
#define OS   50816                 // [BM][64]   glimpse softmax   = 896
#define OBT  51712                 // b_ih+b_hh                    = 512
#define OGBQ 52224
#define OPBQ 52352
#define OGV  52480
#define OPV  52608
#define SMEM_FLOATS 52736          // 210944 bytes

__global__ void __launch_bounds__(NT, 1) ptrnet_main(
    const float* __restrict__ dec, const float* __restrict__ emb,
    const float* __restrict__ h0,  const float* __restrict__ c0,
    const float* __restrict__ Wih, const float* __restrict__ Whh,
    const float* __restrict__ bih, const float* __restrict__ bhh,
    const float* __restrict__ gWq, const float* __restrict__ gbq,
    const float* __restrict__ pWq, const float* __restrict__ pbq,
    const float* __restrict__ gv,  const float* __restrict__ pv,
    float* __restrict__ out)
{
    extern __shared__ float s[];
    __shared__ unsigned long long mask_s[BM];
    __shared__ int idx_s[BM];
    __shared__ int bb_s[BM];

    const int tid = threadIdx.x;
    const int bid = blockIdx.x;

    // ---- prologue ----
    for (int i = tid; i < Hsz * Hsz; i += NT) {
        int r = i >> 7, c = i & 127;
        s[OWQG + r * WQS + c] = gWq[i];
        s[OWQP + r * WQS + c] = pWq[i];
    }
    for (int i = tid; i < 512; i += NT) s[OBT + i] = bih[i] + bhh[i];
    if (tid < 128) {
        s[OGBQ + tid] = gbq[tid];  s[OPBQ + tid] = pbq[tid];
        s[OGV + tid]  = gv[tid];   s[OPV + tid]  = pv[tid];
    }
    for (int i = tid; i < BM * Hsz; i += NT) {
        int m = i >> 7, j = i & 127;
        int bb = min(bid * BM + m, Bsz - 1);
        s[OXH + m * 256 + j]       = dec[bb * Esz + j];
        s[OXH + m * 256 + 128 + j] = h0[bb * Hsz + j];
        s[OC  + m * 128 + j]       = c0[bb * Hsz + j];
    }
    if (tid < BM) {
        mask_s[tid] = 0ull; idx_s[tid] = 0;
        bb_s[tid] = min(bid * BM + tid, Bsz - 1);
    }
    // out[0] = one-hot at l=0
    for (int i = tid; i < BM * Lsz; i += NT) {
        int m = i >> 6, l = i & 63;
        int b = bid * BM + m;
        if (b < Bsz) out[(size_t)b * Lsz + l] = (l == 0) ? 1.0f : 0.0f;
    }
    __syncthreads();

    for (int step = 0; step < NSTEPS; step++) {
        // ---- mask update (uses idx from previous step) ----
        if (tid < BM) {
            unsigned long long mk = mask_s[tid] | (1ull << idx_s[tid]);
            if (idx_s[tid] != 0) mk &= ~1ull;
            mask_s[tid] = mk;
        }

        // ---- phase A: gates[m][o] = Wih[o]·x[m] + Whh[o]·h[m] + btot[o] ----
        {
            const int o = tid;                     // 512 outputs, 1/thread
            float acc[BM];
            float b0 = s[OBT + o];
            #pragma unroll
            for (int m = 0; m < BM; m++) acc[m] = b0;
            const float4* wih4 = reinterpret_cast<const float4*>(Wih + o * Esz);
            #pragma unroll 4
            for (int k4 = 0; k4 < 32; k4++) {
                float4 w = wih4[k4];
                #pragma unroll
                for (int m = 0; m < BM; m++) {
                    float4 xv = *reinterpret_cast<const float4*>(&s[OXH + m * 256 + k4 * 4]);
                    acc[m] += w.x * xv.x + w.y * xv.y + w.z * xv.z + w.w * xv.w;
                }
            }
            const float4* whh4 = reinterpret_cast<const float4*>(Whh + o * Hsz);
            #pragma unroll 4
            for (int k4 = 0; k4 < 32; k4++) {
                float4 w = whh4[k4];
                #pragma unroll
                for (int m = 0; m < BM; m++) {
                    float4 xv = *reinterpret_cast<const float4*>(&s[OXH + m * 256 + 128 + k4 * 4]);
                    acc[m] += w.x * xv.x + w.y * xv.y + w.z * xv.z + w.w * xv.w;
                }
            }
            #pragma unroll
            for (int m = 0; m < BM; m++) s[OG + m * 512 + o] = acc[m];
        }
        __syncthreads();

        // ---- phase B: LSTM pointwise ----
        for (int i = tid; i < BM * Hsz; i += NT) {
            int m = i >> 7, j = i & 127;
            float ig = fsigm(s[OG + m * 512 + j]);
            float fg = fsigm(s[OG + m * 512 + 128 + j]);
            float gg = ftanh(s[OG + m * 512 + 256 + j]);
            float og = fsigm(s[OG + m * 512 + 384 + j]);
            float cn = fg * s[OC + m * 128 + j] + ig * gg;
            s[OC + m * 128 + j] = cn;
            s[OXH + m * 256 + 128 + j] = og * ftanh(cn);   // h_new
        }
        __syncthreads();

        // ---- qg[m][o] = gWq[o]·h_new[m] + gbq[o] ----
        {
            const int o = tid & 127, mg = tid >> 7;
            for (int m = mg; m < BM; m += 4) {
                float acc = s[OGBQ + o];
                #pragma unroll 8
                for (int k4 = 0; k4 < 32; k4++) {
                    float4 w = *reinterpret_cast<const float4*>(&s[OWQG + o * WQS + k4 * 4]);
                    float4 h = *reinterpret_cast<const float4*>(&s[OXH + m * 256 + 128 + k4 * 4]);
                    acc += w.x * h.x + w.y * h.y + w.z * h.z + w.w * h.w;
                }
                s[OQ + m * 128 + o] = acc;
            }
        }
        __syncthreads();

        // ---- ug[m][l] = sum_h gv[h] * tanh(qg[m][h] + e_g[b][l][h]) ----
        for (int task = tid; task < BM * Lsz; task += NT) {
            int m = task >> 6, l = task & 63;
            const float4* eg = reinterpret_cast<const float4*>(
                d_eg + ((size_t)bb_s[m] * Lsz + l) * Hsz);
            float acc = 0.f;
            #pragma unroll 8
            for (int k4 = 0; k4 < 32; k4++) {
                float4 e = eg[k4];
                float4 q = *reinterpret_cast<const float4*>(&s[OQ + m * 128 + k4 * 4]);
                float4 g = *reinterpret_cast<const float4*>(&s[OGV + k4 * 4]);
                acc += g.x * ftanh(q.x + e.x) + g.y * ftanh(q.y + e.y)
                     + g.z * ftanh(q.z + e.z) + g.w * ftanh(q.w + e.w);
            }
            s[OU + task] = acc;
        }
        __syncthreads();

        // ---- glimpse softmax (masked) -> s[OS] ----
        {
            int w = tid >> 5, lane = tid & 31;
            if (w < BM) {
                int m = w;
                unsigned long long mk = mask_s[m];
                float v0 = ((mk >> lane) & 1ull)        ? NEGV : s[OU + m * 64 + lane];
                float v1 = ((mk >> (lane + 32)) & 1ull) ? NEGV : s[OU + m * 64 + 32 + lane];
                float mx = fmaxf(v0, v1);
                for (int off = 16; off; off >>= 1)
                    mx = fmaxf(mx, __shfl_xor_sync(0xffffffffu, mx, off));
                float e0 = __expf(v0 - mx), e1 = __expf(v1 - mx);
                float sum = e0 + e1;
                for (int off = 16; off; off >>= 1)
                    sum += __shfl_xor_sync(0xffffffffu, sum, off);
                float inv = __fdividef(1.f, sum);
                s[OS + m * 64 + lane]      = e0 * inv;
                s[OS + m * 64 + 32 + lane] = e1 * inv;
            }
        }
        __syncthreads();

        // ---- g_l[m][h] = sum_l e_g[b][l][h] * sm[m][l] ----
        {
            const int h = tid & 127, mg = tid >> 7;
            for (int m = mg; m < BM; m += 4) {
                const float* eg = d_eg + ((size_t)bb_s[m] * Lsz) * Hsz + h;
                float acc = 0.f;
                #pragma unroll 8
                for (int l = 0; l < Lsz; l++)
                    acc += eg[l * Hsz] * s[OS + m * 64 + l];
                s[OGL + m * 128 + h] = acc;
            }
        }
        __syncthreads();

        // ---- qp[m][o] = pWq[o]·g_l[m] + pbq[o] ----
        {
            const int o = tid & 127, mg = tid >> 7;
            for (int m = mg; m < BM; m += 4) {
                float acc = s[OPBQ + o];
                #pragma unroll 8
                for (int k4 = 0; k4 < 32; k4++) {
                    float4 w = *reinterpret_cast<const float4*>(&s[OWQP + o * WQS + k4 * 4]);
                    float4 g = *reinterpret_cast<const float4*>(&s[OGL + m * 128 + k4 * 4]);
                    acc += w.x * g.x + w.y * g.y + w.z * g.z + w.w * g.w;
                }
                s[OQ + m * 128 + o] = acc;
            }
        }
        __syncthreads();

        // ---- up[m][l] = sum_h pv[h] * tanh(qp[m][h] + e_p[b][l][h]) ----
        for (int task = tid; task < BM * Lsz; task += NT) {
            int m = task >> 6, l = task & 63;
            const float4* ep = reinterpret_cast<const float4*>(
                d_ep + ((size_t)bb_s[m] * Lsz + l) * Hsz);
            float acc = 0.f;
            #pragma unroll 8
            for (int k4 = 0; k4 < 32; k4++) {
                float4 e = ep[k4];
                float4 q = *reinterpret_cast<const float4*>(&s[OQ + m * 128 + k4 * 4]);
                float4 p = *reinterpret_cast<const float4*>(&s[OPV + k4 * 4]);
                acc += p.x * ftanh(q.x + e.x) + p.y * ftanh(q.y + e.y)
                     + p.z * ftanh(q.z + e.z) + p.w * ftanh(q.w + e.w);
            }
            s[OU + task] = acc;
        }
        __syncthreads();

        // ---- pointer: 10*tanh, mask, softmax, argmax, write probs ----
        {
            int w = tid >> 5, lane = tid & 31;
            if (w < BM) {
                int m = w;
                unsigned long long mk = mask_s[m];
                float r0 = 10.f * ftanh(s[OU + m * 64 + lane]);
                float r1 = 10.f * ftanh(s[OU + m * 64 + 32 + lane]);
                float v0 = ((mk >> lane) & 1ull)        ? NEGV : r0;
                float v1 = ((mk >> (lane + 32)) & 1ull) ? NEGV : r1;
                float mv; int mi;
                if (v0 >= v1) { mv = v0; mi = lane; } else { mv = v1; mi = lane + 32; }
                for (int off = 16; off; off >>= 1) {
                    float ov = __shfl_xor_sync(0xffffffffu, mv, off);
                    int   oi = __shfl_xor_sync(0xffffffffu, mi, off);
                    if (ov > mv || (ov == mv && oi < mi)) { mv = ov; mi = oi; }
                }
                float e0 = __expf(v0 - mv), e1 = __expf(v1 - mv);
                float sum = e0 + e1;
                for (int off = 16; off; off >>= 1)
                    sum += __shfl_xor_sync(0xffffffffu, sum, off);
                float inv = __fdividef(1.f, sum);
                int b = bid * BM + m;
                if (b < Bsz) {
                    float* op = out + ((size_t)(step + 1) * Bsz + b) * Lsz;
                    op[lane]      = e0 * inv;
                    op[lane + 32] = e1 * inv;
                }
                if (lane == 0) idx_s[m] = mi;
            }
        }
        __syncthreads();

        // ---- gather x_new = embedded_inputs[idx][b][:] ----
        for (int i = tid; i < BM * 32; i += NT) {
            int m = i >> 5, e4 = i & 31;
            const float4* src = reinterpret_cast<const float4*>(
                emb + ((size_t)idx_s[m] * Bsz + bb_s[m]) * Esz);
            *reinterpret_cast<float4*>(&s[OXH + m * 256 + e4 * 4]) = src[e4];
        }
        __syncthreads();
    }
}

extern "C" void kernel_launch(void* const* d_in, const int* in_sizes, int n_in,
                              void* d_out, int out_size)
{
    const float* dec   = (const float*)d_in[0];
    const float* emb   = (const float*)d_in[1];
    const float* ctx   = (const float*)d_in[2];
    const float* h0    = (const float*)d_in[3];
    const float* c0    = (const float*)d_in[4];
    const float* Wih   = (const float*)d_in[5];
    const float* Whh   = (const float*)d_in[6];
    const float* bih   = (const float*)d_in[7];
    const float* bhh   = (const float*)d_in[8];
    const float* gWq   = (const float*)d_in[9];
    const float* gbq   = (const float*)d_in[10];
    const float* gWref = (const float*)d_in[11];
    const float* gbref = (const float*)d_in[12];
    const float* gv    = (const float*)d_in[13];
    const float* pWq   = (const float*)d_in[14];
    const float* pbq   = (const float*)d_in[15];
    const float* pWref = (const float*)d_in[16];
    const float* pbref = (const float*)d_in[17];
    const float* pv    = (const float*)d_in[18];
    float* out = (float*)d_out;

    cudaFuncSetAttribute(ptrnet_main, cudaFuncAttributeMaxDynamicSharedMemorySize,
                         SMEM_FLOATS * 4);

    ptrnet_pre<<<Bsz, 128>>>(ctx, gWref, gbref, pWref, pbref);
    ptrnet_main<<<GRID, NT, SMEM_FLOATS * 4>>>(dec, emb, h0, c0, Wih, Whh,
                                               bih, bhh, gWq, gbq, pWq, pbq,
                                               gv, pv, out);
}

// round 2
// speedup vs baseline: 1.4272x; 1.4272x over previous
#include <cuda_runtime.h>
#include <math.h>

#define Bsz 2048
#define Lsz 64
#define Esz 128
#define Hsz 128
#define NSTEPS 126
#define BM 14
#define NT 512
#define GRID 147               // ceil(2048/14)
#define WQS 132                // padded smem row stride (floats) for Wq matrices
#define NEGV -1000000000.0f

// scratch (module-static device arrays: allowed)
__device__ float d_eg[(size_t)Bsz * Lsz * Hsz];   // e_g[b][l][h]
__device__ float d_ep[(size_t)Bsz * Lsz * Hsz];   // e_p[b][l][h]
__device__ float4 d_wt4[64 * 512];                // transposed LSTM weights: [k4][o]

// packed f32x2 FMA (Blackwell): d = a*b + c elementwise, IEEE rn per lane
#define FMA2(d, a, b, c) \
    asm("fma.rn.f32x2 %0, %1, %2, %3;" : "=l"(d) : "l"(a), "l"(b), "l"(c))

__device__ __forceinline__ unsigned long long pack2(float lo, float hi) {
    unsigned long long r;
    asm("mov.b64 %0, {%1, %2};" : "=l"(r) : "f"(lo), "f"(hi));
    return r;
}
__device__ __forceinline__ float hsum2(unsigned long long v) {
    float a, b;
    asm("mov.b64 {%0, %1}, %2;" : "=f"(a), "=f"(b) : "l"(v));
    return a + b;
}

__device__ __forceinline__ float ftanh(float x) {
    // exact at +/-inf; rel err ~1e-6 (EX2 + RCP)
    float e = __expf(2.f * x);
    return 1.f - __fdividef(2.f, e + 1.f);
}
__device__ __forceinline__ float fsigm(float x) {
    return __fdividef(1.f, 1.f + __expf(-x));
}

// ---------------------------------------------------------------------------
// Transpose LSTM weights: d_wt4[k4*512 + o] = concat(Wih,Whh)[o][4k4..4k4+3]
// ---------------------------------------------------------------------------
__global__ void __launch_bounds__(512) ptrnet_prew(
    const float* __restrict__ Wih, const float* __restrict__ Whh)
{
    int i = blockIdx.x * blockDim.x + threadIdx.x;   // 0..32767
    if (i >= 64 * 512) return;
    int k4 = i >> 9, o = i & 511;
    const float* src = (k4 < 32) ? (Wih + o * 128 + (k4 << 2))
                                 : (Whh + o * 128 + ((k4 - 32) << 2));
    d_wt4[i] = *reinterpret_cast<const float4*>(src);
}

// ---------------------------------------------------------------------------
// Precompute e_g/e_p: e[b][l][o] = sum_h Wref[o][h]*context[l][b][h] + bref[o]
// ---------------------------------------------------------------------------
__global__ void __launch_bounds__(128) ptrnet_pre(
    const float* __restrict__ ctx,                          // (L,B,H)
    const float* __restrict__ gWref, const float* __restrict__ gbref,
    const float* __restrict__ pWref, const float* __restrict__ pbref)
{
    __shared__ float cs[Lsz * Hsz];
    const int b = blockIdx.x, t = threadIdx.x;
    for (int l = 0; l < Lsz; l++)
        cs[l * Hsz + t] = ctx[((size_t)l * Bsz + b) * Hsz + t];
    __syncthreads();

    {   // e_g
        float acc[Lsz];
        #pragma unroll
        for (int l = 0; l < Lsz; l++) acc[l] = 0.f;
        const float4* wr = reinterpret_cast<const float4*>(gWref + t * Hsz);
        #pragma unroll 1
        for (int k4 = 0; k4 < 32; k4++) {
            float4 w = wr[k4];
            #pragma unroll
            for (int l = 0; l < Lsz; l++) {
                float4 c = *reinterpret_cast<const float4*>(&cs[l * Hsz + k4 * 4]);
                acc[l] += w.x * c.x + w.y * c.y + w.z * c.z + w.w * c.w;
            }
        }
        float bias = gbref[t];
        #pragma unroll
        for (int l = 0; l < Lsz; l++)
            d_eg[((size_t)b * Lsz + l) * Hsz + t] = acc[l] + bias;
    }
    {   // e_p
        float acc[Lsz];
        #pragma unroll
        for (int l = 0; l < Lsz; l++) acc[l] = 0.f;
        const float4* wr = reinterpret_cast<const float4*>(pWref + t * Hsz);
        #pragma unroll 1
        for (int k4 = 0; k4 < 32; k4++) {
            float4 w = wr[k4];
            #pragma unroll
            for (int l = 0; l < Lsz; l++) {
                float4 c = *reinterpret_cast<const float4*>(&cs[l * Hsz + k4 * 4]);
                acc[l] += w.x * c.x + w.y * c.y + w.z * c.z + w.w * c.w;
            }
        }
        float bias = pbref[t];
        #pragma unroll
        for (int l = 0; l < Lsz; l++)
            d_ep[((size_t)b * Lsz + l) * Hsz + t] = acc[l] + bias;
    }
}

// ---------------------------------------------------------------------------
// Persistent decode kernel
// ---------------------------------------------------------------------------
#define OWQG 0                     // g_Wq padded: 128*132         = 16896
#define OWQP 16896                 // p_Wq padded                  = 16896
#define OXH  33792                 // [BM][256]  x | h             = 3584
#define OG   37376                 // [BM][512]  gates             = 7168
#define OC   44544                 // [BM][128]  cell state        = 1792
#define OQ   46336                 // [BM][128]  qg / qp           = 1792
#define OGL  48128                 // [BM][128]  glimpse g_l       = 1792
#define OU   49920                 // [BM][64]   ug / up           = 896
#define OS   50816                 // [BM][64]   glimpse softmax   = 896
#define OBT  51712                 // b_ih+b_hh                    = 512
#define OGBQ 52224
#define OPBQ 52352
#define OGV  52480
#define OPV  52608
#define SMEM_FLOATS 52736          // 210944 bytes

__global__ void __launch_bounds__(NT, 1) ptrnet_main(
    const float* __restrict__ dec, const float* __restrict__ emb,
    const float* __restrict__ h0,  const float* __restrict__ c0,
    const float* __restrict__ bih, const float* __restrict__ bhh,
    const float* __restrict__ gWq, const float* __restrict__ gbq,
    const float* __restrict__ pWq, const float* __restrict__ pbq,
    const float* __restrict__ gv,  const float* __restrict__ pv,
    float* __restrict__ out)
{
    extern __shared__ float s[];
    __shared__ unsigned long long mask_s[BM];
    __shared__ int idx_s[BM];
    __shared__ int bb_s[BM];

    const int tid = threadIdx.x;
    const int bid = blockIdx.x;

    // ---- prologue ----
    for (int i = tid; i < Hsz * Hsz; i += NT) {
        int r = i >> 7, c = i & 127;
        s[OWQG + r * WQS + c] = gWq[i];
        s[OWQP + r * WQS + c] = pWq[i];
    }
    for (int i = tid; i < 512; i += NT) s[OBT + i] = bih[i] + bhh[i];
    if (tid < 128) {
        s[OGBQ + tid] = gbq[tid];  s[OPBQ + tid] = pbq[tid];
        s[OGV + tid]  = gv[tid];   s[OPV + tid]  = pv[tid];
    }
    for (int i = tid; i < BM * Hsz; i += NT) {
        int m = i >> 7, j = i & 127;
        int bb = min(bid * BM + m, Bsz - 1);
        s[OXH + m * 256 + j]       = dec[bb * Esz + j];
        s[OXH + m * 256 + 128 + j] = h0[bb * Hsz + j];
        s[OC  + m * 128 + j]       = c0[bb * Hsz + j];
    }
    if (tid < BM) {
        mask_s[tid] = 0ull; idx_s[tid] = 0;
        bb_s[tid] = min(bid * BM + tid, Bsz - 1);
    }
    // out[0] = one-hot at l=0
    for (int i = tid; i < BM * Lsz; i += NT) {
        int m = i >> 6, l = i & 63;
        int b = bid * BM + m;
        if (b < Bsz) out[(size_t)b * Lsz + l] = (l == 0) ? 1.0f : 0.0f;
    }
    __syncthreads();

    const int warp = tid >> 5, lane = tid & 31;
    const int grp = lane >> 3, lk = lane & 7;     // 8-lane groups for ug/up

    for (int step = 0; step < NSTEPS; step++) {
        // ---- mask update ----
        if (tid < BM) {
            unsigned long long mk = mask_s[tid] | (1ull << idx_s[tid]);
            if (idx_s[tid] != 0) mk &= ~1ull;
            mask_s[tid] = mk;
        }

        // ---- phase A: gates via transposed weights + packed FMA ----
        {
            const int o = tid;
            unsigned long long acc[BM];
            float b0 = s[OBT + o];
            #pragma unroll
            for (int m = 0; m < BM; m++) acc[m] = pack2(b0, 0.f);
            #pragma unroll 2
            for (int k4 = 0; k4 < 64; k4++) {
                const ulonglong2 w2 =
                    *reinterpret_cast<const ulonglong2*>(&d_wt4[(k4 << 9) + o]);
                #pragma unroll
                for (int m = 0; m < BM; m++) {
                    const ulonglong2 x2 =
                        *reinterpret_cast<const ulonglong2*>(&s[OXH + m * 256 + (k4 << 2)]);
                    FMA2(acc[m], w2.x, x2.x, acc[m]);
                    FMA2(acc[m], w2.y, x2.y, acc[m]);
                }
            }
            #pragma unroll
            for (int m = 0; m < BM; m++) s[OG + m * 512 + o] = hsum2(acc[m]);
        }
        __syncthreads();

        // ---- phase B: LSTM pointwise ----
        for (int i = tid; i < BM * Hsz; i += NT) {
            int m = i >> 7, j = i & 127;
            float ig = fsigm(s[OG + m * 512 + j]);
            float fg = fsigm(s[OG + m * 512 + 128 + j]);
            float gg = ftanh(s[OG + m * 512 + 256 + j]);
            float og = fsigm(s[OG + m * 512 + 384 + j]);
            float cn = fg * s[OC + m * 128 + j] + ig * gg;
            s[OC + m * 128 + j] = cn;
            s[OXH + m * 256 + 128 + j] = og * ftanh(cn);   // h_new
        }
        __syncthreads();

        // ---- qg[m][o] = gWq[o]·h_new[m] + gbq[o] ----
        {
            const int o = tid & 127, mg = tid >> 7;
            for (int m = mg; m < BM; m += 4) {
                unsigned long long a2 = pack2(s[OGBQ + o], 0.f);
                #pragma unroll 8
                for (int k4 = 0; k4 < 32; k4++) {
                    ulonglong2 w2 = *reinterpret_cast<const ulonglong2*>(
                        &s[OWQG + o * WQS + (k4 << 2)]);
                    ulonglong2 h2 = *reinterpret_cast<const ulonglong2*>(
                        &s[OXH + m * 256 + 128 + (k4 << 2)]);
                    FMA2(a2, w2.x, h2.x, a2);
                    FMA2(a2, w2.y, h2.y, a2);
                }
                s[OQ + m * 128 + o] = hsum2(a2);
            }
        }
        __syncthreads();

        // ---- ug: warp-cooperative, coalesced e_g loads ----
        for (int rb = warp * 4 + grp; rb < BM * Lsz; rb += 64) {
            int m = rb >> 6, l = rb & 63;
            const float4* e4 = reinterpret_cast<const float4*>(
                d_eg + ((size_t)bb_s[m] * Lsz + l) * Hsz);
            float acc = 0.f;
            #pragma unroll
            for (int j = 0; j < 4; j++) {
                int k4 = (j << 3) + lk;
                float4 e = e4[k4];
                float4 q = *reinterpret_cast<const float4*>(&s[OQ + m * 128 + (k4 << 2)]);
                float4 g = *reinterpret_cast<const float4*>(&s[OGV + (k4 << 2)]);
                acc += g.x * ftanh(q.x + e.x) + g.y * ftanh(q.y + e.y)
                     + g.z * ftanh(q.z + e.z) + g.w * ftanh(q.w + e.w);
            }
            acc += __shfl_xor_sync(0xffffffffu, acc, 1);
            acc += __shfl_xor_sync(0xffffffffu, acc, 2);
            acc += __shfl_xor_sync(0xffffffffu, acc, 4);
            if (lk == 0) s[OU + rb] = acc;
        }
        __syncthreads();

        // ---- glimpse softmax (masked) -> s[OS] ----
        if (warp < BM) {
            int m = warp;
            unsigned long long mk = mask_s[m];
            float v0 = ((mk >> lane) & 1ull)        ? NEGV : s[OU + m * 64 + lane];
            float v1 = ((mk >> (lane + 32)) & 1ull) ? NEGV : s[OU + m * 64 + 32 + lane];
            float mx = fmaxf(v0, v1);
            for (int off = 16; off; off >>= 1)
                mx = fmaxf(mx, __shfl_xor_sync(0xffffffffu, mx, off));
            float e0 = __expf(v0 - mx), e1 = __expf(v1 - mx);
            float sum = e0 + e1;
            for (int off = 16; off; off >>= 1)
                sum += __shfl_xor_sync(0xffffffffu, sum, off);
            float inv = __fdividef(1.f, sum);
            s[OS + m * 64 + lane]      = e0 * inv;
            s[OS + m * 64 + 32 + lane] = e1 * inv;
        }
        __syncthreads();

        // ---- g_l[m][h] = sum_l e_g[b][l][h] * sm[m][l] ----
        {
            const int h = tid & 127, mg = tid >> 7;
            for (int m = mg; m < BM; m += 4) {
                const float* eg = d_eg + ((size_t)bb_s[m] * Lsz) * Hsz + h;
                float acc = 0.f;
                #pragma unroll 8
                for (int l = 0; l < Lsz; l++)
                    acc += eg[l * Hsz] * s[OS + m * 64 + l];
                s[OGL + m * 128 + h] = acc;
            }
        }
        __syncthreads();

        // ---- qp[m][o] = pWq[o]·g_l[m] + pbq[o] ----
        {
            const int o = tid & 127, mg = tid >> 7;
            for (int m = mg; m < BM; m += 4) {
                unsigned long long a2 = pack2(s[OPBQ + o], 0.f);
                #pragma unroll 8
                for (int k4 = 0; k4 < 32; k4++) {
                    ulonglong2 w2 = *reinterpret_cast<const ulonglong2*>(
                        &s[OWQP + o * WQS + (k4 << 2)]);
                    ulonglong2 g2 = *reinterpret_cast<const ulonglong2*>(
                        &s[OGL + m * 128 + (k4 << 2)]);
                    FMA2(a2, w2.x, g2.x, a2);
                    FMA2(a2, w2.y, g2.y, a2);
                }
                s[OQ + m * 128 + o] = hsum2(a2);
            }
        }
        __syncthreads();

        // ---- up: warp-cooperative, coalesced e_p loads ----
        for (int rb = warp * 4 + grp; rb < BM * Lsz; rb += 64) {
            int m = rb >> 6, l = rb & 63;
            const float4* e4 = reinterpret_cast<const float4*>(
                d_ep + ((size_t)bb_s[m] * Lsz + l) * Hsz);
            float acc = 0.f;
            #pragma unroll
            for (int j = 0; j < 4; j++) {
                int k4 = (j << 3) + lk;
                float4 e = e4[k4];
                float4 q = *reinterpret_cast<const float4*>(&s[OQ + m * 128 + (k4 << 2)]);
                float4 p = *reinterpret_cast<const float4*>(&s[OPV + (k4 << 2)]);
                acc += p.x * ftanh(q.x + e.x) + p.y * ftanh(q.y + e.y)
                     + p.z * ftanh(q.z + e.z) + p.w * ftanh(q.w + e.w);
            }
            acc += __shfl_xor_sync(0xffffffffu, acc, 1);
            acc += __shfl_xor_sync(0xffffffffu, acc, 2);
            acc += __shfl_xor_sync(0xffffffffu, acc, 4);
            if (lk == 0) s[OU + rb] = acc;
        }
        __syncthreads();

        // ---- pointer: 10*tanh, mask, softmax, argmax, write probs ----
        if (warp < BM) {
            int m = warp;
            unsigned long long mk = mask_s[m];
            float r0 = 10.f * tanhf(s[OU + m * 64 + lane]);
            float r1 = 10.f * tanhf(s[OU + m * 64 + 32 + lane]);
            float v0 = ((mk >> lane) & 1ull)        ? NEGV : r0;
            float v1 = ((mk >> (lane + 32)) & 1ull) ? NEGV : r1;
            float mv; int mi;
            if (v0 >= v1) { mv = v0; mi = lane; } else { mv = v1; mi = lane + 32; }
            for (int off = 16; off; off >>= 1) {
                float ov = __shfl_xor_sync(0xffffffffu, mv, off);
                int   oi = __shfl_xor_sync(0xffffffffu, mi, off);
                if (ov > mv || (ov == mv && oi < mi)) { mv = ov; mi = oi; }
            }
            float e0 = __expf(v0 - mv), e1 = __expf(v1 - mv);
            float sum = e0 + e1;
            for (int off = 16; off; off >>= 1)
                sum += __shfl_xor_sync(0xffffffffu, sum, off);
            float inv = __fdividef(1.f, sum);
            int b = bid * BM + m;
            if (b < Bsz) {
                float* op = out + ((size_t)(step + 1) * Bsz + b) * Lsz;
                op[lane]      = e0 * inv;
                op[lane + 32] = e1 * inv;
            }
            if (lane == 0) idx_s[m] = mi;
        }
        __syncthreads();

        // ---- gather x_new = embedded_inputs[idx][b][:] ----
        for (int i = tid; i < BM * 32; i += NT) {
            int m = i >> 5, e4i = i & 31;
            const float4* src = reinterpret_cast<const float4*>(
                emb + ((size_t)idx_s[m] * Bsz + bb_s[m]) * Esz);
            *reinterpret_cast<float4*>(&s[OXH + m * 256 + e4i * 4]) = src[e4i];
        }
        __syncthreads();
    }
}

extern "C" void kernel_launch(void* const* d_in, const int* in_sizes, int n_in,
                              void* d_out, int out_size)
{
    const float* dec   = (const float*)d_in[0];
    const float* emb   = (const float*)d_in[1];
    const float* ctx   = (const float*)d_in[2];
    const float* h0    = (const float*)d_in[3];
    const float* c0    = (const float*)d_in[4];
    const float* Wih   = (const float*)d_in[5];
    const float* Whh   = (const float*)d_in[6];
    const float* bih   = (const float*)d_in[7];
    const float* bhh   = (const float*)d_in[8];
    const float* gWq   = (const float*)d_in[9];
    const float* gbq   = (const float*)d_in[10];
    const float* gWref = (const float*)d_in[11];
    const float* gbref = (const float*)d_in[12];
    const float* gv    = (const float*)d_in[13];
    const float* pWq   = (const float*)d_in[14];
    const float* pbq   = (const float*)d_in[15];
    const float* pWref = (const float*)d_in[16];
    const float* pbref = (const float*)d_in[17];
    const float* pv    = (const float*)d_in[18];
    float* out = (float*)d_out;

    cudaFuncSetAttribute(ptrnet_main, cudaFuncAttributeMaxDynamicSharedMemorySize,
                         SMEM_FLOATS * 4);

    ptrnet_prew<<<64, 512>>>(Wih, Whh);
    ptrnet_pre<<<Bsz, 128>>>(ctx, gWref, gbref, pWref, pbref);
    ptrnet_main<<<GRID, NT, SMEM_FLOATS * 4>>>(dec, emb, h0, c0,
                                               bih, bhh, gWq, gbq, pWq, pbq,
                                               gv, pv, out);
}

// round 3
// speedup vs baseline: 1.5647x; 1.0963x over previous
#include <cuda_runtime.h>
#include <math.h>

#define Bsz 2048
#define Lsz 64
#define Esz 128
#define Hsz 128
#define NSTEPS 126
#define BM 14
#define NT 1024
#define GRID 147               // ceil(2048/14)
#define NEGV -1000000000.0f

// scratch (module-static device arrays: allowed)
__device__ float d_eg[(size_t)Bsz * Lsz * Hsz];   // e_g[b][l][h]
__device__ float d_ep[(size_t)Bsz * Lsz * Hsz];   // e_p[b][l][h]
__device__ float4 d_wt4[64 * 512];                // transposed LSTM weights [k4][o]
__device__ float4 d_wq4[2 * 32 * 128];            // transposed gWq|pWq [which][k4][o]

// packed f32x2 FMA (Blackwell): d = a*b + c elementwise, IEEE rn per lane
#define FMA2(d, a, b, c) \
    asm("fma.rn.f32x2 %0, %1, %2, %3;" : "=l"(d) : "l"(a), "l"(b), "l"(c))

__device__ __forceinline__ unsigned long long pack2(float lo, float hi) {
    unsigned long long r;
    asm("mov.b64 %0, {%1, %2};" : "=l"(r) : "f"(lo), "f"(hi));
    return r;
}
__device__ __forceinline__ float hsum2(unsigned long long v) {
    float a, b;
    asm("mov.b64 {%0, %1}, %2;" : "=f"(a), "=f"(b) : "l"(v));
    return a + b;
}

__device__ __forceinline__ float ftanh(float x) {
    // exact at +/-inf; rel err ~1e-6 (EX2 + RCP)
    float e = __expf(2.f * x);
    return 1.f - __fdividef(2.f, e + 1.f);
}
__device__ __forceinline__ float fsigm(float x) {
    return __fdividef(1.f, 1.f + __expf(-x));
}

// ---------------------------------------------------------------------------
// Transpose LSTM weights + Wq matrices into coalesced [k][o] layouts
// ---------------------------------------------------------------------------
__global__ void __launch_bounds__(512) ptrnet_prew(
    const float* __restrict__ Wih, const float* __restrict__ Whh,
    const float* __restrict__ gWq, const float* __restrict__ pWq)
{
    int i = blockIdx.x * blockDim.x + threadIdx.x;   // 0..40959
    if (i < 64 * 512) {
        int k4 = i >> 9, o = i & 511;
        const float* src = (k4 < 32) ? (Wih + o * 128 + (k4 << 2))
                                     : (Whh + o * 128 + ((k4 - 32) << 2));
        d_wt4[i] = *reinterpret_cast<const float4*>(src);
    } else if (i < 64 * 512 + 2 * 4096) {
        int j = i - 64 * 512;
        int which = j >> 12, r = j & 4095;
        int k4 = r >> 7, o = r & 127;
        const float* W = which ? pWq : gWq;
        d_wq4[which * 4096 + k4 * 128 + o] =
            *reinterpret_cast<const float4*>(W + o * 128 + (k4 << 2));
    }
}

// ---------------------------------------------------------------------------
// Precompute e_g/e_p: e[b][l][o] = sum_h Wref[o][h]*context[l][b][h] + bref[o]
// ---------------------------------------------------------------------------
__global__ void __launch_bounds__(128) ptrnet_pre(
    const float* __restrict__ ctx,                          // (L,B,H)
    const float* __restrict__ gWref, const float* __restrict__ gbref,
    const float* __restrict__ pWref, const float* __restrict__ pbref)
{
    __shared__ float cs[Lsz * Hsz];
    const int b = blockIdx.x, t = threadIdx.x;
    for (int l = 0; l < Lsz; l++)
        cs[l * Hsz + t] = ctx[((size_t)l * Bsz + b) * Hsz + t];
    __syncthreads();

    {   // e_g
        float acc[Lsz];
        #pragma unroll
        for (int l = 0; l < Lsz; l++) acc[l] = 0.f;
        const float4* wr = reinterpret_cast<const float4*>(gWref + t * Hsz);
        #pragma unroll 1
        for (int k4 = 0; k4 < 32; k4++) {
            float4 w = wr[k4];
            #pragma unroll
            for (int l = 0; l < Lsz; l++) {
                float4 c = *reinterpret_cast<const float4*>(&cs[l * Hsz + k4 * 4]);
                acc[l] += w.x * c.x + w.y * c.y + w.z * c.z + w.w * c.w;
            }
        }
        float bias = gbref[t];
        #pragma unroll
        for (int l = 0; l < Lsz; l++)
            d_eg[((size_t)b * Lsz + l) * Hsz + t] = acc[l] + bias;
    }
    {   // e_p
        float acc[Lsz];
        #pragma unroll
        for (int l = 0; l < Lsz; l++) acc[l] = 0.f;
        const float4* wr = reinterpret_cast<const float4*>(pWref + t * Hsz);
        #pragma unroll 1
        for (int k4 = 0; k4 < 32; k4++) {
            float4 w = wr[k4];
            #pragma unroll
            for (int l = 0; l < Lsz; l++) {
                float4 c = *reinterpret_cast<const float4*>(&cs[l * Hsz + k4 * 4]);
                acc[l] += w.x * c.x + w.y * c.y + w.z * c.z + w.w * c.w;
            }
        }
        float bias = pbref[t];
        #pragma unroll
        for (int l = 0; l < Lsz; l++)
            d_ep[((size_t)b * Lsz + l) * Hsz + t] = acc[l] + bias;
    }
}

// ---------------------------------------------------------------------------
// Persistent decode kernel, 1024 threads, split-K LSTM GEMV
// smem float offsets:
// ---------------------------------------------------------------------------
#define OXH  0                     // [BM][256]  x | h           3584
#define OG   3584                  // [BM][512]  gates half0     7168
#define OG2  10752                 // [BM][512]  gates half1     7168
#define OC   17920                 // [BM][128]                  1792
#define OQ   19712                 // [BM][128]  qg / qp         1792
#define OGL  21504                 // [BM][128]  glimpse         1792
#define OU   23296                 // [BM][64]                   896
#define OS   24192                 // [BM][64]                   896
#define OBT  25088                 // b_ih+b_hh                  512
#define OGBQ 25600
#define OPBQ 25728
#define OGV  25856
#define OPV  25984
#define SMEM_FLOATS 26112          // 104448 bytes

__global__ void __launch_bounds__(NT, 1) ptrnet_main(
    const float* __restrict__ dec, const float* __restrict__ emb,
    const float* __restrict__ h0,  const float* __restrict__ c0,
    const float* __restrict__ bih, const float* __restrict__ bhh,
    const float* __restrict__ gbq, const float* __restrict__ pbq,
    const float* __restrict__ gv,  const float* __restrict__ pv,
    float* __restrict__ out)
{
    extern __shared__ float s[];
    __shared__ unsigned long long mask_s[BM];
    __shared__ int idx_s[BM];
    __shared__ int bb_s[BM];

    const int tid = threadIdx.x;
    const int bid = blockIdx.x;

    // ---- prologue ----
    for (int i = tid; i < 512; i += NT) s[OBT + i] = bih[i] + bhh[i];
    if (tid < 128) {
        s[OGBQ + tid] = gbq[tid];  s[OPBQ + tid] = pbq[tid];
        s[OGV + tid]  = gv[tid];   s[OPV + tid]  = pv[tid];
    }
    for (int i = tid; i < BM * Hsz; i += NT) {
        int m = i >> 7, j = i & 127;
        int bb = min(bid * BM + m, Bsz - 1);
        s[OXH + m * 256 + j]       = dec[bb * Esz + j];
        s[OXH + m * 256 + 128 + j] = h0[bb * Hsz + j];
        s[OC  + m * 128 + j]       = c0[bb * Hsz + j];
    }
    if (tid < BM) {
        mask_s[tid] = 0ull; idx_s[tid] = 0;
        bb_s[tid] = min(bid * BM + tid, Bsz - 1);
    }
    // out[0] = one-hot at l=0
    for (int i = tid; i < BM * Lsz; i += NT) {
        int m = i >> 6, l = i & 63;
        int b = bid * BM + m;
        if (b < Bsz) out[(size_t)b * Lsz + l] = (l == 0) ? 1.0f : 0.0f;
    }
    __syncthreads();

    const int warp = tid >> 5, lane = tid & 31;
    const int grp = lane >> 3, lk = lane & 7;     // 8-lane groups for ug/up
    const int o512 = tid & 511, hf = tid >> 9;    // phase-A split-K mapping
    const int o128 = tid & 127, mg8 = tid >> 7;   // qg/qp/g_l mapping

    for (int step = 0; step < NSTEPS; step++) {
        // ---- mask update ----
        if (tid < BM) {
            unsigned long long mk = mask_s[tid] | (1ull << idx_s[tid]);
            if (idx_s[tid] != 0) mk &= ~1ull;
            mask_s[tid] = mk;
        }

        // ---- phase A: gates split-K. hf=0: Wih·x + b ; hf=1: Whh·h ----
        {
            unsigned long long acc[BM];
            float b0 = hf ? 0.f : s[OBT + o512];
            #pragma unroll
            for (int m = 0; m < BM; m++) acc[m] = pack2(b0, 0.f);
            const int k4base = hf << 5;          // 0 or 32
            const int xoff = hf << 7;            // x at +0, h at +128
            #pragma unroll 4
            for (int kk = 0; kk < 32; kk++) {
                const ulonglong2 w2 = *reinterpret_cast<const ulonglong2*>(
                    &d_wt4[((k4base + kk) << 9) + o512]);
                #pragma unroll
                for (int m = 0; m < BM; m++) {
                    const ulonglong2 x2 = *reinterpret_cast<const ulonglong2*>(
                        &s[OXH + m * 256 + xoff + (kk << 2)]);
                    FMA2(acc[m], w2.x, x2.x, acc[m]);
                    FMA2(acc[m], w2.y, x2.y, acc[m]);
                }
            }
            const int og = hf ? OG2 : OG;
            #pragma unroll
            for (int m = 0; m < BM; m++) s[og + m * 512 + o512] = hsum2(acc[m]);
        }
        __syncthreads();

        // ---- phase B: LSTM pointwise (combine halves) ----
        for (int i = tid; i < BM * Hsz; i += NT) {
            int m = i >> 7, j = i & 127;
            float ig = fsigm(s[OG + m * 512 + j]       + s[OG2 + m * 512 + j]);
            float fg = fsigm(s[OG + m * 512 + 128 + j] + s[OG2 + m * 512 + 128 + j]);
            float gg = ftanh(s[OG + m * 512 + 256 + j] + s[OG2 + m * 512 + 256 + j]);
            float og = fsigm(s[OG + m * 512 + 384 + j] + s[OG2 + m * 512 + 384 + j]);
            float cn = fg * s[OC + m * 128 + j] + ig * gg;
            s[OC + m * 128 + j] = cn;
            s[OXH + m * 256 + 128 + j] = og * ftanh(cn);   // h_new
        }
        __syncthreads();

        // ---- qg[m][o] = gWq[o]·h_new[m] + gbq[o]  (transposed global Wq) ----
        {
            for (int m = mg8; m < BM; m += 8) {
                unsigned long long a2 = pack2(s[OGBQ + o128], 0.f);
                #pragma unroll 8
                for (int k4 = 0; k4 < 32; k4++) {
                    ulonglong2 w2 = *reinterpret_cast<const ulonglong2*>(
                        &d_wq4[k4 * 128 + o128]);
                    ulonglong2 h2 = *reinterpret_cast<const ulonglong2*>(
                        &s[OXH + m * 256 + 128 + (k4 << 2)]);
                    FMA2(a2, w2.x, h2.x, a2);
                    FMA2(a2, w2.y, h2.y, a2);
                }
                s[OQ + m * 128 + o128] = hsum2(a2);
            }
        }
        __syncthreads();

        // ---- ug: warp-cooperative, coalesced e_g loads ----
        for (int rb = warp * 4 + grp; rb < BM * Lsz; rb += 128) {
            int m = rb >> 6, l = rb & 63;
            const float4* e4 = reinterpret_cast<const float4*>(
                d_eg + ((size_t)bb_s[m] * Lsz + l) * Hsz);
            float acc = 0.f;
            #pragma unroll
            for (int j = 0; j < 4; j++) {
                int k4 = (j << 3) + lk;
                float4 e = e4[k4];
                float4 q = *reinterpret_cast<const float4*>(&s[OQ + m * 128 + (k4 << 2)]);
                float4 g = *reinterpret_cast<const float4*>(&s[OGV + (k4 << 2)]);
                acc += g.x * ftanh(q.x + e.x) + g.y * ftanh(q.y + e.y)
                     + g.z * ftanh(q.z + e.z) + g.w * ftanh(q.w + e.w);
            }
            acc += __shfl_xor_sync(0xffffffffu, acc, 1);
            acc += __shfl_xor_sync(0xffffffffu, acc, 2);
            acc += __shfl_xor_sync(0xffffffffu, acc, 4);
            if (lk == 0) s[OU + rb] = acc;
        }
        __syncthreads();

        // ---- glimpse softmax (masked) -> s[OS] ----
        if (warp < BM) {
            int m = warp;
            unsigned long long mk = mask_s[m];
            float v0 = ((mk >> lane) & 1ull)        ? NEGV : s[OU + m * 64 + lane];
            float v1 = ((mk >> (lane + 32)) & 1ull) ? NEGV : s[OU + m * 64 + 32 + lane];
            float mx = fmaxf(v0, v1);
            for (int off = 16; off; off >>= 1)
                mx = fmaxf(mx, __shfl_xor_sync(0xffffffffu, mx, off));
            float e0 = __expf(v0 - mx), e1 = __expf(v1 - mx);
            float sum = e0 + e1;
            for (int off = 16; off; off >>= 1)
                sum += __shfl_xor_sync(0xffffffffu, sum, off);
            float inv = __fdividef(1.f, sum);
            s[OS + m * 64 + lane]      = e0 * inv;
            s[OS + m * 64 + 32 + lane] = e1 * inv;
        }
        __syncthreads();

        // ---- g_l[m][h] = sum_l e_g[b][l][h] * sm[m][l] ----
        {
            for (int m = mg8; m < BM; m += 8) {
                const float* eg = d_eg + ((size_t)bb_s[m] * Lsz) * Hsz + o128;
                float acc = 0.f;
                #pragma unroll 8
                for (int l = 0; l < Lsz; l++)
                    acc += eg[l * Hsz] * s[OS + m * 64 + l];
                s[OGL + m * 128 + o128] = acc;
            }
        }
        __syncthreads();

        // ---- qp[m][o] = pWq[o]·g_l[m] + pbq[o] ----
        {
            for (int m = mg8; m < BM; m += 8) {
                unsigned long long a2 = pack2(s[OPBQ + o128], 0.f);
                #pragma unroll 8
                for (int k4 = 0; k4 < 32; k4++) {
                    ulonglong2 w2 = *reinterpret_cast<const ulonglong2*>(
                        &d_wq4[4096 + k4 * 128 + o128]);
                    ulonglong2 g2 = *reinterpret_cast<const ulonglong2*>(
                        &s[OGL + m * 128 + (k4 << 2)]);
                    FMA2(a2, w2.x, g2.x, a2);
                    FMA2(a2, w2.y, g2.y, a2);
                }
                s[OQ + m * 128 + o128] = hsum2(a2);
            }
        }
        __syncthreads();

        // ---- up: warp-cooperative, coalesced e_p loads ----
        for (int rb = warp * 4 + grp; rb < BM * Lsz; rb += 128) {
            int m = rb >> 6, l = rb & 63;
            const float4* e4 = reinterpret_cast<const float4*>(
                d_ep + ((size_t)bb_s[m] * Lsz + l) * Hsz);
            float acc = 0.f;
            #pragma unroll
            for (int j = 0; j < 4; j++) {
                int k4 = (j << 3) + lk;
                float4 e = e4[k4];
                float4 q = *reinterpret_cast<const float4*>(&s[OQ + m * 128 + (k4 << 2)]);
                float4 p = *reinterpret_cast<const float4*>(&s[OPV + (k4 << 2)]);
                acc += p.x * ftanh(q.x + e.x) + p.y * ftanh(q.y + e.y)
                     + p.z * ftanh(q.z + e.z) + p.w * ftanh(q.w + e.w);
            }
            acc += __shfl_xor_sync(0xffffffffu, acc, 1);
            acc += __shfl_xor_sync(0xffffffffu, acc, 2);
            acc += __shfl_xor_sync(0xffffffffu, acc, 4);
            if (lk == 0) s[OU + rb] = acc;
        }
        __syncthreads();

        // ---- pointer: 10*tanh, mask, softmax, argmax, write probs ----
        if (warp < BM) {
            int m = warp;
            unsigned long long mk = mask_s[m];
            float r0 = 10.f * tanhf(s[OU + m * 64 + lane]);
            float r1 = 10.f * tanhf(s[OU + m * 64 + 32 + lane]);
            float v0 = ((mk >> lane) & 1ull)        ? NEGV : r0;
            float v1 = ((mk >> (lane + 32)) & 1ull) ? NEGV : r1;
            float mv; int mi;
            if (v0 >= v1) { mv = v0; mi = lane; } else { mv = v1; mi = lane + 32; }
            for (int off = 16; off; off >>= 1) {
                float ov = __shfl_xor_sync(0xffffffffu, mv, off);
                int   oi = __shfl_xor_sync(0xffffffffu, mi, off);
                if (ov > mv || (ov == mv && oi < mi)) { mv = ov; mi = oi; }
            }
            float e0 = __expf(v0 - mv), e1 = __expf(v1 - mv);
            float sum = e0 + e1;
            for (int off = 16; off; off >>= 1)
                sum += __shfl_xor_sync(0xffffffffu, sum, off);
            float inv = __fdividef(1.f, sum);
            int b = bid * BM + m;
            if (b < Bsz) {
                float* op = out + ((size_t)(step + 1) * Bsz + b) * Lsz;
                op[lane]      = e0 * inv;
                op[lane + 32] = e1 * inv;
            }
            if (lane == 0) idx_s[m] = mi;
        }
        __syncthreads();

        // ---- gather x_new = embedded_inputs[idx][b][:] ----
        for (int i = tid; i < BM * 32; i += NT) {
            int m = i >> 5, e4i = i & 31;
            const float4* src = reinterpret_cast<const float4*>(
                emb + ((size_t)idx_s[m] * Bsz + bb_s[m]) * Esz);
            *reinterpret_cast<float4*>(&s[OXH + m * 256 + e4i * 4]) = src[e4i];
        }
        __syncthreads();
    }
}

extern "C" void kernel_launch(void* const* d_in, const int* in_sizes, int n_in,
                              void* d_out, int out_size)
{
    const float* dec   = (const float*)d_in[0];
    const float* emb   = (const float*)d_in[1];
    const float* ctx   = (const float*)d_in[2];
    const float* h0    = (const float*)d_in[3];
    const float* c0    = (const float*)d_in[4];
    const float* Wih   = (const float*)d_in[5];
    const float* Whh   = (const float*)d_in[6];
    const float* bih   = (const float*)d_in[7];
    const float* bhh   = (const float*)d_in[8];
    const float* gWq   = (const float*)d_in[9];
    const float* gbq   = (const float*)d_in[10];
    const float* gWref = (const float*)d_in[11];
    const float* gbref = (const float*)d_in[12];
    const float* gv    = (const float*)d_in[13];
    const float* pWq   = (const float*)d_in[14];
    const float* pbq   = (const float*)d_in[15];
    const float* pWref = (const float*)d_in[16];
    const float* pbref = (const float*)d_in[17];
    const float* pv    = (const float*)d_in[18];
    float* out = (float*)d_out;

    cudaFuncSetAttribute(ptrnet_main, cudaFuncAttributeMaxDynamicSharedMemorySize,
                         SMEM_FLOATS * 4);

    ptrnet_prew<<<80, 512>>>(Wih, Whh, gWq, pWq);
    ptrnet_pre<<<Bsz, 128>>>(ctx, gWref, gbref, pWref, pbref);
    ptrnet_main<<<GRID, NT, SMEM_FLOATS * 4>>>(dec, emb, h0, c0,
                                               bih, bhh, gbq, pbq,
                                               gv, pv, out);
}

// round 5
// speedup vs baseline: 1.9710x; 1.2597x over previous
#include <cuda_runtime.h>
#include <math.h>

#define Bsz 2048
#define Lsz 64
#define Esz 128
#define Hsz 128
#define NSTEPS 126
#define BM 14
#define NT 1024
#define GRID 147               // ceil(2048/14)
#define NEGV -1000000000.0f

// scratch (module-static device arrays: allowed)
__device__ float d_eg[(size_t)Bsz * Lsz * Hsz];   // e_g[b][l][h]
__device__ float d_ep[(size_t)Bsz * Lsz * Hsz];   // e_p[b][l][h]
__device__ float4 d_wt4[64 * 512];                // transposed LSTM weights [k4][o]
__device__ float4 d_wq4[2 * 32 * 128];            // transposed gWq|pWq [which][k4][o]

// packed f32x2 FMA (Blackwell): d = a*b + c elementwise, IEEE rn per lane
#define FMA2(d, a, b, c) \
    asm("fma.rn.f32x2 %0, %1, %2, %3;" : "=l"(d) : "l"(a), "l"(b), "l"(c))

__device__ __forceinline__ unsigned long long pack2(float lo, float hi) {
    unsigned long long r;
    asm("mov.b64 %0, {%1, %2};" : "=l"(r) : "f"(lo), "f"(hi));
    return r;
}
__device__ __forceinline__ float hsum2(unsigned long long v) {
    float a, b;
    asm("mov.b64 {%0, %1}, %2;" : "=f"(a), "=f"(b) : "l"(v));
    return a + b;
}

__device__ __forceinline__ float ftanh(float x) {
    float e = __expf(2.f * x);
    return 1.f - __fdividef(2.f, e + 1.f);
}
__device__ __forceinline__ float fsigm(float x) {
    return __fdividef(1.f, 1.f + __expf(-x));
}

// ---------------------------------------------------------------------------
// Transpose LSTM weights + Wq matrices into coalesced [k][o] layouts
// ---------------------------------------------------------------------------
__global__ void __launch_bounds__(512) ptrnet_prew(
    const float* __restrict__ Wih, const float* __restrict__ Whh,
    const float* __restrict__ gWq, const float* __restrict__ pWq)
{
    int i = blockIdx.x * blockDim.x + threadIdx.x;
    if (i < 64 * 512) {
        int k4 = i >> 9, o = i & 511;
        const float* src = (k4 < 32) ? (Wih + o * 128 + (k4 << 2))
                                     : (Whh + o * 128 + ((k4 - 32) << 2));
        d_wt4[i] = *reinterpret_cast<const float4*>(src);
    } else if (i < 64 * 512 + 2 * 4096) {
        int j = i - 64 * 512;
        int which = j >> 12, r = j & 4095;
        int k4 = r >> 7, o = r & 127;
        const float* W = which ? pWq : gWq;
        d_wq4[which * 4096 + k4 * 128 + o] =
            *reinterpret_cast<const float4*>(W + o * 128 + (k4 << 2));
    }
}

// ---------------------------------------------------------------------------
// Precompute e_g/e_p
// ---------------------------------------------------------------------------
__global__ void __launch_bounds__(128) ptrnet_pre(
    const float* __restrict__ ctx,
    const float* __restrict__ gWref, const float* __restrict__ gbref,
    const float* __restrict__ pWref, const float* __restrict__ pbref)
{
    __shared__ float cs[Lsz * Hsz];
    const int b = blockIdx.x, t = threadIdx.x;
    for (int l = 0; l < Lsz; l++)
        cs[l * Hsz + t] = ctx[((size_t)l * Bsz + b) * Hsz + t];
    __syncthreads();

    {
        float acc[Lsz];
        #pragma unroll
        for (int l = 0; l < Lsz; l++) acc[l] = 0.f;
        const float4* wr = reinterpret_cast<const float4*>(gWref + t * Hsz);
        #pragma unroll 1
        for (int k4 = 0; k4 < 32; k4++) {
            float4 w = wr[k4];
            #pragma unroll
            for (int l = 0; l < Lsz; l++) {
                float4 c = *reinterpret_cast<const float4*>(&cs[l * Hsz + k4 * 4]);
                acc[l] += w.x * c.x + w.y * c.y + w.z * c.z + w.w * c.w;
            }
        }
        float bias = gbref[t];
        #pragma unroll
        for (int l = 0; l < Lsz; l++)
            d_eg[((size_t)b * Lsz + l) * Hsz + t] = acc[l] + bias;
    }
    {
        float acc[Lsz];
        #pragma unroll
        for (int l = 0; l < Lsz; l++) acc[l] = 0.f;
        const float4* wr = reinterpret_cast<const float4*>(pWref + t * Hsz);
        #pragma unroll 1
        for (int k4 = 0; k4 < 32; k4++) {
            float4 w = wr[k4];
            #pragma unroll
            for (int l = 0; l < Lsz; l++) {
                float4 c = *reinterpret_cast<const float4*>(&cs[l * Hsz + k4 * 4]);
                acc[l] += w.x * c.x + w.y * c.y + w.z * c.z + w.w * c.w;
            }
        }
        float bias = pbref[t];
        #pragma unroll
        for (int l = 0; l < Lsz; l++)
            d_ep[((size_t)b * Lsz + l) * Hsz + t] = acc[l] + bias;
    }
}

// ---------------------------------------------------------------------------
// Persistent decode kernel, 1024 threads, split-K LSTM GEMV, masked-work skip
// (warp-uniform compacted loops: all shuffles execute with full warps)
// ---------------------------------------------------------------------------
#define OXH  0                     // [BM][256]  x | h           3584
#define OG   3584                  // [BM][512]  gates half0     7168
#define OG2  10752                 // [BM][512]  gates half1     7168
#define OC   17920                 // [BM][128]                  1792
#define OQ   19712                 // [BM][128]  qg / qp         1792
#define OGL  21504                 // [BM][128]  glimpse         1792
#define OU   23296                 // [BM][64]                   896
#define OS   24192                 // [BM][64]                   896
#define OBT  25088                 // b_ih+b_hh                  512
#define OGBQ 25600
#define OPBQ 25728
#define OGV  25856
#define OPV  25984
#define SMEM_FLOATS 26112          // 104448 bytes

__global__ void __launch_bounds__(NT, 1) ptrnet_main(
    const float* __restrict__ dec, const float* __restrict__ emb,
    const float* __restrict__ h0,  const float* __restrict__ c0,
    const float* __restrict__ bih, const float* __restrict__ bhh,
    const float* __restrict__ gbq, const float* __restrict__ pbq,
    const float* __restrict__ gv,  const float* __restrict__ pv,
    float* __restrict__ out)
{
    extern __shared__ float s[];
    __shared__ unsigned long long mask_s[BM];
    __shared__ int idx_s[BM];
    __shared__ int bb_s[BM];
    __shared__ int cnt_s[BM];
    __shared__ int off_s[BM];
    __shared__ int R_s;
    __shared__ unsigned short rowlist[BM * Lsz];

    const int tid = threadIdx.x;
    const int bid = blockIdx.x;

    // ---- prologue ----
    for (int i = tid; i < 512; i += NT) s[OBT + i] = bih[i] + bhh[i];
    if (tid < 128) {
        s[OGBQ + tid] = gbq[tid];  s[OPBQ + tid] = pbq[tid];
        s[OGV + tid]  = gv[tid];   s[OPV + tid]  = pv[tid];
    }
    for (int i = tid; i < BM * Hsz; i += NT) {
        int m = i >> 7, j = i & 127;
        int bb = min(bid * BM + m, Bsz - 1);
        s[OXH + m * 256 + j]       = dec[bb * Esz + j];
        s[OXH + m * 256 + 128 + j] = h0[bb * Hsz + j];
        s[OC  + m * 128 + j]       = c0[bb * Hsz + j];
    }
    if (tid < BM) {
        mask_s[tid] = 0ull; idx_s[tid] = 0;
        bb_s[tid] = min(bid * BM + tid, Bsz - 1);
    }
    for (int i = tid; i < BM * Lsz; i += NT) {
        int m = i >> 6, l = i & 63;
        int b = bid * BM + m;
        if (b < Bsz) out[(size_t)b * Lsz + l] = (l == 0) ? 1.0f : 0.0f;
    }
    __syncthreads();

    const int warp = tid >> 5, lane = tid & 31;
    const int grp = lane >> 3, lk = lane & 7;
    const int o512 = tid & 511, hf = tid >> 9;
    const int o128 = tid & 127, mg8 = tid >> 7;

    for (int step = 0; step < NSTEPS; step++) {
        // ---- mask update + per-row unmasked count ----
        if (tid < BM) {
            unsigned long long mk = mask_s[tid] | (1ull << idx_s[tid]);
            if (idx_s[tid] != 0) mk &= ~1ull;
            mask_s[tid] = mk;
            cnt_s[tid] = 64 - __popcll(mk);
        }

        // ---- phase A: gates split-K ----
        {
            unsigned long long acc[BM];
            float b0 = hf ? 0.f : s[OBT + o512];
            #pragma unroll
            for (int m = 0; m < BM; m++) acc[m] = pack2(b0, 0.f);
            const int k4base = hf << 5;
            const int xoff = hf << 7;
            #pragma unroll 4
            for (int kk = 0; kk < 32; kk++) {
                const ulonglong2 w2 = *reinterpret_cast<const ulonglong2*>(
                    &d_wt4[((k4base + kk) << 9) + o512]);
                #pragma unroll
                for (int m = 0; m < BM; m++) {
                    const ulonglong2 x2 = *reinterpret_cast<const ulonglong2*>(
                        &s[OXH + m * 256 + xoff + (kk << 2)]);
                    FMA2(acc[m], w2.x, x2.x, acc[m]);
                    FMA2(acc[m], w2.y, x2.y, acc[m]);
                }
            }
            const int og = hf ? OG2 : OG;
            #pragma unroll
            for (int m = 0; m < BM; m++) s[og + m * 512 + o512] = hsum2(acc[m]);
        }
        __syncthreads();

        // ---- phase B: LSTM pointwise + build compact unmasked rowlist ----
        for (int i = tid; i < BM * Hsz; i += NT) {
            int m = i >> 7, j = i & 127;
            float ig = fsigm(s[OG + m * 512 + j]       + s[OG2 + m * 512 + j]);
            float fg = fsigm(s[OG + m * 512 + 128 + j] + s[OG2 + m * 512 + 128 + j]);
            float gg = ftanh(s[OG + m * 512 + 256 + j] + s[OG2 + m * 512 + 256 + j]);
            float og = fsigm(s[OG + m * 512 + 384 + j] + s[OG2 + m * 512 + 384 + j]);
            float cn = fg * s[OC + m * 128 + j] + ig * gg;
            s[OC + m * 128 + j] = cn;
            s[OXH + m * 256 + 128 + j] = og * ftanh(cn);
        }
        if (tid < BM) {
            int off = 0;
            for (int j = 0; j < tid; j++) off += cnt_s[j];
            off_s[tid] = off;
            unsigned long long unm = ~mask_s[tid];
            int k = 0;
            while (unm) {
                int l = __ffsll((long long)unm) - 1;
                rowlist[off + k] = (unsigned short)((tid << 6) | l);
                k++;
                unm &= unm - 1;
            }
        }
        if (tid == 0) {
            int R = 0;
            #pragma unroll
            for (int j = 0; j < BM; j++) R += cnt_s[j];
            R_s = R;
        }
        __syncthreads();

        const int Rv = R_s;                 // uniform across block after barrier
        const int nIter = (Rv + 127) >> 7;  // warp-uniform trip count

        // ---- qg[m][o] = gWq[o]·h_new[m] + gbq[o] ----
        {
            for (int m = mg8; m < BM; m += 8) {
                unsigned long long a2 = pack2(s[OGBQ + o128], 0.f);
                #pragma unroll 8
                for (int k4 = 0; k4 < 32; k4++) {
                    ulonglong2 w2 = *reinterpret_cast<const ulonglong2*>(
                        &d_wq4[k4 * 128 + o128]);
                    ulonglong2 h2 = *reinterpret_cast<const ulonglong2*>(
                        &s[OXH + m * 256 + 128 + (k4 << 2)]);
                    FMA2(a2, w2.x, h2.x, a2);
                    FMA2(a2, w2.y, h2.y, a2);
                }
                s[OQ + m * 128 + o128] = hsum2(a2);
            }
        }
        __syncthreads();

        // ---- ug: only unmasked rows (uniform trip count, predicated write) ----
        for (int k = 0; k < nIter; k++) {
            int r = warp * 4 + grp + (k << 7);
            bool valid = (r < Rv);
            int e = rowlist[valid ? r : 0];
            int m = e >> 6, l = e & 63;
            const float4* e4 = reinterpret_cast<const float4*>(
                d_eg + ((size_t)bb_s[m] * Lsz + l) * Hsz);
            float acc = 0.f;
            #pragma unroll
            for (int j = 0; j < 4; j++) {
                int k4 = (j << 3) + lk;
                float4 ev = e4[k4];
                float4 q = *reinterpret_cast<const float4*>(&s[OQ + m * 128 + (k4 << 2)]);
                float4 g = *reinterpret_cast<const float4*>(&s[OGV + (k4 << 2)]);
                acc += g.x * ftanh(q.x + ev.x) + g.y * ftanh(q.y + ev.y)
                     + g.z * ftanh(q.z + ev.z) + g.w * ftanh(q.w + ev.w);
            }
            acc += __shfl_xor_sync(0xffffffffu, acc, 1);
            acc += __shfl_xor_sync(0xffffffffu, acc, 2);
            acc += __shfl_xor_sync(0xffffffffu, acc, 4);
            if (valid && lk == 0) s[OU + (m << 6) + l] = acc;
        }
        __syncthreads();

        // ---- glimpse softmax (masked) ----
        if (warp < BM) {
            int m = warp;
            unsigned long long mk = mask_s[m];
            float v0 = ((mk >> lane) & 1ull)        ? NEGV : s[OU + m * 64 + lane];
            float v1 = ((mk >> (lane + 32)) & 1ull) ? NEGV : s[OU + m * 64 + 32 + lane];
            float mx = fmaxf(v0, v1);
            for (int off = 16; off; off >>= 1)
                mx = fmaxf(mx, __shfl_xor_sync(0xffffffffu, mx, off));
            float e0 = __expf(v0 - mx), e1 = __expf(v1 - mx);
            float sum = e0 + e1;
            for (int off = 16; off; off >>= 1)
                sum += __shfl_xor_sync(0xffffffffu, sum, off);
            float inv = __fdividef(1.f, sum);
            s[OS + m * 64 + lane]      = e0 * inv;
            s[OS + m * 64 + 32 + lane] = e1 * inv;
        }
        __syncthreads();

        // ---- g_l[m][h] = sum_l e_g[b][l][h] * sm[m][l] (skip sm==0) ----
        {
            for (int m = mg8; m < BM; m += 8) {
                const float* eg = d_eg + ((size_t)bb_s[m] * Lsz) * Hsz + o128;
                float acc = 0.f;
                if (Rv > 0) {
                    int off = off_s[m], cn = cnt_s[m];
                    for (int j = 0; j < cn; j++) {
                        int l = rowlist[off + j] & 63;
                        acc += eg[(size_t)l * Hsz] * s[OS + m * 64 + l];
                    }
                } else {
                    #pragma unroll 8
                    for (int l = 0; l < Lsz; l++)
                        acc += eg[l * Hsz] * s[OS + m * 64 + l];
                }
                s[OGL + m * 128 + o128] = acc;
            }
        }
        __syncthreads();

        // ---- qp[m][o] = pWq[o]·g_l[m] + pbq[o] ----
        {
            for (int m = mg8; m < BM; m += 8) {
                unsigned long long a2 = pack2(s[OPBQ + o128], 0.f);
                #pragma unroll 8
                for (int k4 = 0; k4 < 32; k4++) {
                    ulonglong2 w2 = *reinterpret_cast<const ulonglong2*>(
                        &d_wq4[4096 + k4 * 128 + o128]);
                    ulonglong2 g2 = *reinterpret_cast<const ulonglong2*>(
                        &s[OGL + m * 128 + (k4 << 2)]);
                    FMA2(a2, w2.x, g2.x, a2);
                    FMA2(a2, w2.y, g2.y, a2);
                }
                s[OQ + m * 128 + o128] = hsum2(a2);
            }
        }
        __syncthreads();

        // ---- up: only unmasked rows (uniform trip count) ----
        for (int k = 0; k < nIter; k++) {
            int r = warp * 4 + grp + (k << 7);
            bool valid = (r < Rv);
            int e = rowlist[valid ? r : 0];
            int m = e >> 6, l = e & 63;
            const float4* e4 = reinterpret_cast<const float4*>(
                d_ep + ((size_t)bb_s[m] * Lsz + l) * Hsz);
            float acc = 0.f;
            #pragma unroll
            for (int j = 0; j < 4; j++) {
                int k4 = (j << 3) + lk;
                float4 ev = e4[k4];
                float4 q = *reinterpret_cast<const float4*>(&s[OQ + m * 128 + (k4 << 2)]);
                float4 p = *reinterpret_cast<const float4*>(&s[OPV + (k4 << 2)]);
                acc += p.x * ftanh(q.x + ev.x) + p.y * ftanh(q.y + ev.y)
                     + p.z * ftanh(q.z + ev.z) + p.w * ftanh(q.w + ev.w);
            }
            acc += __shfl_xor_sync(0xffffffffu, acc, 1);
            acc += __shfl_xor_sync(0xffffffffu, acc, 2);
            acc += __shfl_xor_sync(0xffffffffu, acc, 4);
            if (valid && lk == 0) s[OU + (m << 6) + l] = acc;
        }
        __syncthreads();

        // ---- pointer: 10*tanh, mask, softmax, argmax, write probs ----
        if (warp < BM) {
            int m = warp;
            unsigned long long mk = mask_s[m];
            float r0 = 10.f * tanhf(s[OU + m * 64 + lane]);
            float r1 = 10.f * tanhf(s[OU + m * 64 + 32 + lane]);
            float v0 = ((mk >> lane) & 1ull)        ? NEGV : r0;
            float v1 = ((mk >> (lane + 32)) & 1ull) ? NEGV : r1;
            float mv; int mi;
            if (v0 >= v1) { mv = v0; mi = lane; } else { mv = v1; mi = lane + 32; }
            for (int off = 16; off; off >>= 1) {
                float ov = __shfl_xor_sync(0xffffffffu, mv, off);
                int   oi = __shfl_xor_sync(0xffffffffu, mi, off);
                if (ov > mv || (ov == mv && oi < mi)) { mv = ov; mi = oi; }
            }
            float e0 = __expf(v0 - mv), e1 = __expf(v1 - mv);
            float sum = e0 + e1;
            for (int off = 16; off; off >>= 1)
                sum += __shfl_xor_sync(0xffffffffu, sum, off);
            float inv = __fdividef(1.f, sum);
            int b = bid * BM + m;
            if (b < Bsz) {
                float* op = out + ((size_t)(step + 1) * Bsz + b) * Lsz;
                op[lane]      = e0 * inv;
                op[lane + 32] = e1 * inv;
            }
            if (lane == 0) idx_s[m] = mi;
        }
        __syncthreads();

        // ---- gather x_new ----
        for (int i = tid; i < BM * 32; i += NT) {
            int m = i >> 5, e4i = i & 31;
            const float4* src = reinterpret_cast<const float4*>(
                emb + ((size_t)idx_s[m] * Bsz + bb_s[m]) * Esz);
            *reinterpret_cast<float4*>(&s[OXH + m * 256 + e4i * 4]) = src[e4i];
        }
        __syncthreads();
    }
}

extern "C" void kernel_launch(void* const* d_in, const int* in_sizes, int n_in,
                              void* d_out, int out_size)
{
    const float* dec   = (const float*)d_in[0];
    const float* emb   = (const float*)d_in[1];
    const float* ctx   = (const float*)d_in[2];
    const float* h0    = (const float*)d_in[3];
    const float* c0    = (const float*)d_in[4];
    const float* Wih   = (const float*)d_in[5];
    const float* Whh   = (const float*)d_in[6];
    const float* bih   = (const float*)d_in[7];
    const float* bhh   = (const float*)d_in[8];
    const float* gWq   = (const float*)d_in[9];
    const float* gbq   = (const float*)d_in[10];
    const float* gWref = (const float*)d_in[11];
    const float* gbref = (const float*)d_in[12];
    const float* gv    = (const float*)d_in[13];
    const float* pWq   = (const float*)d_in[14];
    const float* pbq   = (const float*)d_in[15];
    const float* pWref = (const float*)d_in[16];
    const float* pbref = (const float*)d_in[17];
    const float* pv    = (const float*)d_in[18];
    float* out = (float*)d_out;

    cudaFuncSetAttribute(ptrnet_main, cudaFuncAttributeMaxDynamicSharedMemorySize,
                         SMEM_FLOATS * 4);

    ptrnet_prew<<<80, 512>>>(Wih, Whh, gWq, pWq);
    ptrnet_pre<<<Bsz, 128>>>(ctx, gWref, gbref, pWref, pbref);
    ptrnet_main<<<GRID, NT, SMEM_FLOATS * 4>>>(dec, emb, h0, c0,
                                               bih, bhh, gbq, pbq,
                                               gv, pv, out);
}

// round 6
// speedup vs baseline: 1.9816x; 1.0054x over previous
#include <cuda_runtime.h>
#include <math.h>

#define Bsz 2048
#define Lsz 64
#define Esz 128
#define Hsz 128
#define NSTEPS 126
#define BM 14
#define NT 1024
#define GRID 147               // ceil(2048/14)
#define NEGV -1000000000.0f

// scratch (module-static device arrays: allowed)
__device__ float d_eg[(size_t)Bsz * Lsz * Hsz];   // e_g[b][l][h]
__device__ float d_ep[(size_t)Bsz * Lsz * Hsz];   // e_p[b][l][h]
__device__ float4 d_wt4[64 * 512];                // transposed LSTM weights [k4][o]
__device__ float4 d_wq4[2 * 32 * 128];            // transposed gWq|pWq [which][k4][o]

// packed f32x2 FMA (Blackwell): d = a*b + c elementwise, IEEE rn per lane
#define FMA2(d, a, b, c) \
    asm("fma.rn.f32x2 %0, %1, %2, %3;" : "=l"(d) : "l"(a), "l"(b), "l"(c))

__device__ __forceinline__ unsigned long long pack2(float lo, float hi) {
    unsigned long long r;
    asm("mov.b64 %0, {%1, %2};" : "=l"(r) : "f"(lo), "f"(hi));
    return r;
}
__device__ __forceinline__ float hsum2(unsigned long long v) {
    float a, b;
    asm("mov.b64 {%0, %1}, %2;" : "=f"(a), "=f"(b) : "l"(v));
    return a + b;
}

__device__ __forceinline__ float ftanh(float x) {
    float e = __expf(2.f * x);
    return 1.f - __fdividef(2.f, e + 1.f);
}
__device__ __forceinline__ float fsigm(float x) {
    return __fdividef(1.f, 1.f + __expf(-x));
}

// ---------------------------------------------------------------------------
// Transpose LSTM weights + Wq matrices into coalesced [k][o] layouts
// ---------------------------------------------------------------------------
__global__ void __launch_bounds__(512) ptrnet_prew(
    const float* __restrict__ Wih, const float* __restrict__ Whh,
    const float* __restrict__ gWq, const float* __restrict__ pWq)
{
    int i = blockIdx.x * blockDim.x + threadIdx.x;
    if (i < 64 * 512) {
        int k4 = i >> 9, o = i & 511;
        const float* src = (k4 < 32) ? (Wih + o * 128 + (k4 << 2))
                                     : (Whh + o * 128 + ((k4 - 32) << 2));
        d_wt4[i] = *reinterpret_cast<const float4*>(src);
    } else if (i < 64 * 512 + 2 * 4096) {
        int j = i - 64 * 512;
        int which = j >> 12, r = j & 4095;
        int k4 = r >> 7, o = r & 127;
        const float* W = which ? pWq : gWq;
        d_wq4[which * 4096 + k4 * 128 + o] =
            *reinterpret_cast<const float4*>(W + o * 128 + (k4 << 2));
    }
}

// ---------------------------------------------------------------------------
// Precompute e_g/e_p
// ---------------------------------------------------------------------------
__global__ void __launch_bounds__(128) ptrnet_pre(
    const float* __restrict__ ctx,
    const float* __restrict__ gWref, const float* __restrict__ gbref,
    const float* __restrict__ pWref, const float* __restrict__ pbref)
{
    __shared__ float cs[Lsz * Hsz];
    const int b = blockIdx.x, t = threadIdx.x;
    for (int l = 0; l < Lsz; l++)
        cs[l * Hsz + t] = ctx[((size_t)l * Bsz + b) * Hsz + t];
    __syncthreads();

    {
        float acc[Lsz];
        #pragma unroll
        for (int l = 0; l < Lsz; l++) acc[l] = 0.f;
        const float4* wr = reinterpret_cast<const float4*>(gWref + t * Hsz);
        #pragma unroll 1
        for (int k4 = 0; k4 < 32; k4++) {
            float4 w = wr[k4];
            #pragma unroll
            for (int l = 0; l < Lsz; l++) {
                float4 c = *reinterpret_cast<const float4*>(&cs[l * Hsz + k4 * 4]);
                acc[l] += w.x * c.x + w.y * c.y + w.z * c.z + w.w * c.w;
            }
        }
        float bias = gbref[t];
        #pragma unroll
        for (int l = 0; l < Lsz; l++)
            d_eg[((size_t)b * Lsz + l) * Hsz + t] = acc[l] + bias;
    }
    {
        float acc[Lsz];
        #pragma unroll
        for (int l = 0; l < Lsz; l++) acc[l] = 0.f;
        const float4* wr = reinterpret_cast<const float4*>(pWref + t * Hsz);
        #pragma unroll 1
        for (int k4 = 0; k4 < 32; k4++) {
            float4 w = wr[k4];
            #pragma unroll
            for (int l = 0; l < Lsz; l++) {
                float4 c = *reinterpret_cast<const float4*>(&cs[l * Hsz + k4 * 4]);
                acc[l] += w.x * c.x + w.y * c.y + w.z * c.z + w.w * c.w;
            }
        }
        float bias = pbref[t];
        #pragma unroll
        for (int l = 0; l < Lsz; l++)
            d_ep[((size_t)b * Lsz + l) * Hsz + t] = acc[l] + bias;
    }
}

// ---------------------------------------------------------------------------
// Persistent decode kernel, 1024 threads, split-K LSTM GEMV, masked-work skip,
// terminal-state early exit (mask full => output exactly uniform 1/64 forever)
// ---------------------------------------------------------------------------
#define OXH  0                     // [BM][256]  x | h           3584
#define OG   3584                  // [BM][512]  gates half0     7168
#define OG2  10752                 // [BM][512]  gates half1     7168
#define OC   17920                 // [BM][128]                  1792
#define OQ   19712                 // [BM][128]  qg / qp         1792
#define OGL  21504                 // [BM][128]  glimpse         1792
#define OU   23296                 // [BM][64]                   896
#define OS   24192                 // [BM][64]                   896
#define OBT  25088                 // b_ih+b_hh                  512
#define OGBQ 25600
#define OPBQ 25728
#define OGV  25856
#define OPV  25984
#define SMEM_FLOATS 26112          // 104448 bytes

__global__ void __launch_bounds__(NT, 1) ptrnet_main(
    const float* __restrict__ dec, const float* __restrict__ emb,
    const float* __restrict__ h0,  const float* __restrict__ c0,
    const float* __restrict__ bih, const float* __restrict__ bhh,
    const float* __restrict__ gbq, const float* __restrict__ pbq,
    const float* __restrict__ gv,  const float* __restrict__ pv,
    float* __restrict__ out)
{
    extern __shared__ float s[];
    __shared__ unsigned long long mask_s[BM];
    __shared__ int idx_s[BM];
    __shared__ int bb_s[BM];
    __shared__ int cnt_s[BM];
    __shared__ int off_s[BM];
    __shared__ int R_s;
    __shared__ unsigned short rowlist[BM * Lsz];

    const int tid = threadIdx.x;
    const int bid = blockIdx.x;

    // ---- prologue ----
    for (int i = tid; i < 512; i += NT) s[OBT + i] = bih[i] + bhh[i];
    if (tid < 128) {
        s[OGBQ + tid] = gbq[tid];  s[OPBQ + tid] = pbq[tid];
        s[OGV + tid]  = gv[tid];   s[OPV + tid]  = pv[tid];
    }
    for (int i = tid; i < BM * Hsz; i += NT) {
        int m = i >> 7, j = i & 127;
        int bb = min(bid * BM + m, Bsz - 1);
        s[OXH + m * 256 + j]       = dec[bb * Esz + j];
        s[OXH + m * 256 + 128 + j] = h0[bb * Hsz + j];
        s[OC  + m * 128 + j]       = c0[bb * Hsz + j];
    }
    if (tid < BM) {
        mask_s[tid] = 0ull; idx_s[tid] = 0;
        bb_s[tid] = min(bid * BM + tid, Bsz - 1);
    }
    for (int i = tid; i < BM * Lsz; i += NT) {
        int m = i >> 6, l = i & 63;
        int b = bid * BM + m;
        if (b < Bsz) out[(size_t)b * Lsz + l] = (l == 0) ? 1.0f : 0.0f;
    }
    __syncthreads();

    const int warp = tid >> 5, lane = tid & 31;
    const int grp = lane >> 3, lk = lane & 7;
    const int o512 = tid & 511, hf = tid >> 9;
    const int o128 = tid & 127, mg8 = tid >> 7;

    for (int step = 0; step < NSTEPS; step++) {
        // ---- mask update + per-row unmasked count ----
        if (tid < BM) {
            unsigned long long mk = mask_s[tid] | (1ull << idx_s[tid]);
            if (idx_s[tid] != 0) mk &= ~1ull;
            mask_s[tid] = mk;
            cnt_s[tid] = 64 - __popcll(mk);
        }

        // ---- phase A: gates split-K ----
        {
            unsigned long long acc[BM];
            float b0 = hf ? 0.f : s[OBT + o512];
            #pragma unroll
            for (int m = 0; m < BM; m++) acc[m] = pack2(b0, 0.f);
            const int k4base = hf << 5;
            const int xoff = hf << 7;
            #pragma unroll 8
            for (int kk = 0; kk < 32; kk++) {
                const ulonglong2 w2 = *reinterpret_cast<const ulonglong2*>(
                    &d_wt4[((k4base + kk) << 9) + o512]);
                #pragma unroll
                for (int m = 0; m < BM; m++) {
                    const ulonglong2 x2 = *reinterpret_cast<const ulonglong2*>(
                        &s[OXH + m * 256 + xoff + (kk << 2)]);
                    FMA2(acc[m], w2.x, x2.x, acc[m]);
                    FMA2(acc[m], w2.y, x2.y, acc[m]);
                }
            }
            const int og = hf ? OG2 : OG;
            #pragma unroll
            for (int m = 0; m < BM; m++) s[og + m * 512 + o512] = hsum2(acc[m]);
        }
        __syncthreads();

        // ---- phase B: LSTM pointwise + build compact unmasked rowlist ----
        for (int i = tid; i < BM * Hsz; i += NT) {
            int m = i >> 7, j = i & 127;
            float ig = fsigm(s[OG + m * 512 + j]       + s[OG2 + m * 512 + j]);
            float fg = fsigm(s[OG + m * 512 + 128 + j] + s[OG2 + m * 512 + 128 + j]);
            float gg = ftanh(s[OG + m * 512 + 256 + j] + s[OG2 + m * 512 + 256 + j]);
            float og = fsigm(s[OG + m * 512 + 384 + j] + s[OG2 + m * 512 + 384 + j]);
            float cn = fg * s[OC + m * 128 + j] + ig * gg;
            s[OC + m * 128 + j] = cn;
            s[OXH + m * 256 + 128 + j] = og * ftanh(cn);
        }
        if (tid < BM) {
            int off = 0;
            for (int j = 0; j < tid; j++) off += cnt_s[j];
            off_s[tid] = off;
            unsigned long long unm = ~mask_s[tid];
            int k = 0;
            while (unm) {
                int l = __ffsll((long long)unm) - 1;
                rowlist[off + k] = (unsigned short)((tid << 6) | l);
                k++;
                unm &= unm - 1;
            }
        }
        if (tid == 0) {
            int R = 0;
            #pragma unroll
            for (int j = 0; j < BM; j++) R += cnt_s[j];
            R_s = R;
        }
        __syncthreads();

        const int Rv = R_s;                 // uniform across block after barrier
        const int nIter = (Rv + 127) >> 7;  // warp-uniform trip count

        // ---- terminal state: all rows fully masked => outputs are exactly
        //      uniform 1/64 for this and ALL remaining steps. Burst + exit. ----
        if (Rv == 0) {
            const float u = 0.015625f;      // 1/64 exact
            for (int st = step + 1; st <= NSTEPS; st++) {
                float* orow = out + (size_t)st * Bsz * Lsz;
                for (int i = tid; i < BM * Lsz; i += NT) {
                    int m = i >> 6;
                    int b = bid * BM + m;
                    if (b < Bsz) orow[(size_t)b * Lsz + (i & 63)] = u;
                }
            }
            return;
        }

        // ---- qg[m][o] = gWq[o]·h_new[m] + gbq[o] ----
        {
            for (int m = mg8; m < BM; m += 8) {
                unsigned long long a2 = pack2(s[OGBQ + o128], 0.f);
                #pragma unroll 8
                for (int k4 = 0; k4 < 32; k4++) {
                    ulonglong2 w2 = *reinterpret_cast<const ulonglong2*>(
                        &d_wq4[k4 * 128 + o128]);
                    ulonglong2 h2 = *reinterpret_cast<const ulonglong2*>(
                        &s[OXH + m * 256 + 128 + (k4 << 2)]);
                    FMA2(a2, w2.x, h2.x, a2);
                    FMA2(a2, w2.y, h2.y, a2);
                }
                s[OQ + m * 128 + o128] = hsum2(a2);
            }
        }
        __syncthreads();

        // ---- ug: only unmasked rows (uniform trip count, predicated write) ----
        for (int k = 0; k < nIter; k++) {
            int r = warp * 4 + grp + (k << 7);
            bool valid = (r < Rv);
            int e = rowlist[valid ? r : 0];
            int m = e >> 6, l = e & 63;
            const float4* e4 = reinterpret_cast<const float4*>(
                d_eg + ((size_t)bb_s[m] * Lsz + l) * Hsz);
            float acc = 0.f;
            #pragma unroll
            for (int j = 0; j < 4; j++) {
                int k4 = (j << 3) + lk;
                float4 ev = e4[k4];
                float4 q = *reinterpret_cast<const float4*>(&s[OQ + m * 128 + (k4 << 2)]);
                float4 g = *reinterpret_cast<const float4*>(&s[OGV + (k4 << 2)]);
                acc += g.x * ftanh(q.x + ev.x) + g.y * ftanh(q.y + ev.y)
                     + g.z * ftanh(q.z + ev.z) + g.w * ftanh(q.w + ev.w);
            }
            acc += __shfl_xor_sync(0xffffffffu, acc, 1);
            acc += __shfl_xor_sync(0xffffffffu, acc, 2);
            acc += __shfl_xor_sync(0xffffffffu, acc, 4);
            if (valid && lk == 0) s[OU + (m << 6) + l] = acc;
        }
        __syncthreads();

        // ---- glimpse softmax (masked) ----
        if (warp < BM) {
            int m = warp;
            unsigned long long mk = mask_s[m];
            float v0 = ((mk >> lane) & 1ull)        ? NEGV : s[OU + m * 64 + lane];
            float v1 = ((mk >> (lane + 32)) & 1ull) ? NEGV : s[OU + m * 64 + 32 + lane];
            float mx = fmaxf(v0, v1);
            for (int off = 16; off; off >>= 1)
                mx = fmaxf(mx, __shfl_xor_sync(0xffffffffu, mx, off));
            float e0 = __expf(v0 - mx), e1 = __expf(v1 - mx);
            float sum = e0 + e1;
            for (int off = 16; off; off >>= 1)
                sum += __shfl_xor_sync(0xffffffffu, sum, off);
            float inv = __fdividef(1.f, sum);
            s[OS + m * 64 + lane]      = e0 * inv;
            s[OS + m * 64 + 32 + lane] = e1 * inv;
        }
        __syncthreads();

        // ---- g_l[m][h] = sum_l e_g[b][l][h] * sm[m][l] (skip sm==0) ----
        {
            for (int m = mg8; m < BM; m += 8) {
                const float* eg = d_eg + ((size_t)bb_s[m] * Lsz) * Hsz + o128;
                float acc = 0.f;
                int off = off_s[m], cn = cnt_s[m];
                for (int j = 0; j < cn; j++) {
                    int l = rowlist[off + j] & 63;
                    acc += eg[(size_t)l * Hsz] * s[OS + m * 64 + l];
                }
                s[OGL + m * 128 + o128] = acc;
            }
        }
        __syncthreads();

        // ---- qp[m][o] = pWq[o]·g_l[m] + pbq[o] ----
        {
            for (int m = mg8; m < BM; m += 8) {
                unsigned long long a2 = pack2(s[OPBQ + o128], 0.f);
                #pragma unroll 8
                for (int k4 = 0; k4 < 32; k4++) {
                    ulonglong2 w2 = *reinterpret_cast<const ulonglong2*>(
                        &d_wq4[4096 + k4 * 128 + o128]);
                    ulonglong2 g2 = *reinterpret_cast<const ulonglong2*>(
                        &s[OGL + m * 128 + (k4 << 2)]);
                    FMA2(a2, w2.x, g2.x, a2);
                    FMA2(a2, w2.y, g2.y, a2);
                }
                s[OQ + m * 128 + o128] = hsum2(a2);
            }
        }
        __syncthreads();

        // ---- up: only unmasked rows (uniform trip count) ----
        for (int k = 0; k < nIter; k++) {
            int r = warp * 4 + grp + (k << 7);
            bool valid = (r < Rv);
            int e = rowlist[valid ? r : 0];
            int m = e >> 6, l = e & 63;
            const float4* e4 = reinterpret_cast<const float4*>(
                d_ep + ((size_t)bb_s[m] * Lsz + l) * Hsz);
            float acc = 0.f;
            #pragma unroll
            for (int j = 0; j < 4; j++) {
                int k4 = (j << 3) + lk;
                float4 ev = e4[k4];
                float4 q = *reinterpret_cast<const float4*>(&s[OQ + m * 128 + (k4 << 2)]);
                float4 p = *reinterpret_cast<const float4*>(&s[OPV + (k4 << 2)]);
                acc += p.x * ftanh(q.x + ev.x) + p.y * ftanh(q.y + ev.y)
                     + p.z * ftanh(q.z + ev.z) + p.w * ftanh(q.w + ev.w);
            }
            acc += __shfl_xor_sync(0xffffffffu, acc, 1);
            acc += __shfl_xor_sync(0xffffffffu, acc, 2);
            acc += __shfl_xor_sync(0xffffffffu, acc, 4);
            if (valid && lk == 0) s[OU + (m << 6) + l] = acc;
        }
        __syncthreads();

        // ---- pointer: 10*tanh, mask, softmax, argmax, write probs ----
        if (warp < BM) {
            int m = warp;
            unsigned long long mk = mask_s[m];
            float r0 = 10.f * tanhf(s[OU + m * 64 + lane]);
            float r1 = 10.f * tanhf(s[OU + m * 64 + 32 + lane]);
            float v0 = ((mk >> lane) & 1ull)        ? NEGV : r0;
            float v1 = ((mk >> (lane + 32)) & 1ull) ? NEGV : r1;
            float mv; int mi;
            if (v0 >= v1) { mv = v0; mi = lane; } else { mv = v1; mi = lane + 32; }
            for (int off = 16; off; off >>= 1) {
                float ov = __shfl_xor_sync(0xffffffffu, mv, off);
                int   oi = __shfl_xor_sync(0xffffffffu, mi, off);
                if (ov > mv || (ov == mv && oi < mi)) { mv = ov; mi = oi; }
            }
            float e0 = __expf(v0 - mv), e1 = __expf(v1 - mv);
            float sum = e0 + e1;
            for (int off = 16; off; off >>= 1)
                sum += __shfl_xor_sync(0xffffffffu, sum, off);
            float inv = __fdividef(1.f, sum);
            int b = bid * BM + m;
            if (b < Bsz) {
                float* op = out + ((size_t)(step + 1) * Bsz + b) * Lsz;
                op[lane]      = e0 * inv;
                op[lane + 32] = e1 * inv;
            }
            if (lane == 0) idx_s[m] = mi;
        }
        __syncthreads();

        // ---- gather x_new ----
        for (int i = tid; i < BM * 32; i += NT) {
            int m = i >> 5, e4i = i & 31;
            const float4* src = reinterpret_cast<const float4*>(
                emb + ((size_t)idx_s[m] * Bsz + bb_s[m]) * Esz);
            *reinterpret_cast<float4*>(&s[OXH + m * 256 + e4i * 4]) = src[e4i];
        }
        __syncthreads();
    }
}

extern "C" void kernel_launch(void* const* d_in, const int* in_sizes, int n_in,
                              void* d_out, int out_size)
{
    const float* dec   = (const float*)d_in[0];
    const float* emb   = (const float*)d_in[1];
    const float* ctx   = (const float*)d_in[2];
    const float* h0    = (const float*)d_in[3];
    const float* c0    = (const float*)d_in[4];
    const float* Wih   = (const float*)d_in[5];
    const float* Whh   = (const float*)d_in[6];
    const float* bih   = (const float*)d_in[7];
    const float* bhh   = (const float*)d_in[8];
    const float* gWq   = (const float*)d_in[9];
    const float* gbq   = (const float*)d_in[10];
    const float* gWref = (const float*)d_in[11];
    const float* gbref = (const float*)d_in[12];
    const float* gv    = (const float*)d_in[13];
    const float* pWq   = (const float*)d_in[14];
    const float* pbq   = (const float*)d_in[15];
    const float* pWref = (const float*)d_in[16];
    const float* pbref = (const float*)d_in[17];
    const float* pv    = (const float*)d_in[18];
    float* out = (float*)d_out;

    cudaFuncSetAttribute(ptrnet_main, cudaFuncAttributeMaxDynamicSharedMemorySize,
                         SMEM_FLOATS * 4);

    ptrnet_prew<<<80, 512>>>(Wih, Whh, gWq, pWq);
    ptrnet_pre<<<Bsz, 128>>>(ctx, gWref, gbref, pWref, pbref);
    ptrnet_main<<<GRID, NT, SMEM_FLOATS * 4>>>(dec, emb, h0, c0,
                                               bih, bhh, gbq, pbq,
                                               gv, pv, out);
}

// round 7
// speedup vs baseline: 2.0392x; 1.0291x over previous
#include <cuda_runtime.h>
#include <math.h>

#define Bsz 2048
#define Lsz 64
#define Esz 128
#define Hsz 128
#define NSTEPS 126
#define BM 14
#define NT 1024
#define GRID 147               // ceil(2048/14)
#define NEGV -1000000000.0f

// scratch (module-static device arrays: allowed)
__device__ float d_eg[(size_t)Bsz * Lsz * Hsz];   // e_g[b][l][h]
__device__ float d_ep[(size_t)Bsz * Lsz * Hsz];   // e_p[b][l][h]
__device__ float4 d_wt4[64 * 512];                // transposed LSTM weights [k4][o] (Wih rows 0..31, Whh rows 32..63)
__device__ float4 d_wq4[2 * 32 * 128];            // transposed gWq|pWq [which][k4][o]
__device__ float  d_P[(size_t)Bsz * Lsz * 512];   // P[b][l][o] = Wih·emb[l,b] + bt   (256MB)
__device__ float  d_P0[(size_t)Bsz * 512];        // P0[b][o]   = Wih·dec[b] + bt

// packed f32x2 FMA (Blackwell): d = a*b + c elementwise, IEEE rn per lane
#define FMA2(d, a, b, c) \
    asm("fma.rn.f32x2 %0, %1, %2, %3;" : "=l"(d) : "l"(a), "l"(b), "l"(c))

__device__ __forceinline__ unsigned long long pack2(float lo, float hi) {
    unsigned long long r;
    asm("mov.b64 %0, {%1, %2};" : "=l"(r) : "f"(lo), "f"(hi));
    return r;
}
__device__ __forceinline__ float hsum2(unsigned long long v) {
    float a, b;
    asm("mov.b64 {%0, %1}, %2;" : "=f"(a), "=f"(b) : "l"(v));
    return a + b;
}

__device__ __forceinline__ float ftanh(float x) {
    float e = __expf(2.f * x);
    return 1.f - __fdividef(2.f, e + 1.f);
}
__device__ __forceinline__ float fsigm(float x) {
    return __fdividef(1.f, 1.f + __expf(-x));
}

// ---------------------------------------------------------------------------
// Transpose LSTM weights + Wq matrices into coalesced [k][o] layouts
// ---------------------------------------------------------------------------
__global__ void __launch_bounds__(512) ptrnet_prew(
    const float* __restrict__ Wih, const float* __restrict__ Whh,
    const float* __restrict__ gWq, const float* __restrict__ pWq)
{
    int i = blockIdx.x * blockDim.x + threadIdx.x;
    if (i < 64 * 512) {
        int k4 = i >> 9, o = i & 511;
        const float* src = (k4 < 32) ? (Wih + o * 128 + (k4 << 2))
                                     : (Whh + o * 128 + ((k4 - 32) << 2));
        d_wt4[i] = *reinterpret_cast<const float4*>(src);
    } else if (i < 64 * 512 + 2 * 4096) {
        int j = i - 64 * 512;
        int which = j >> 12, r = j & 4095;
        int k4 = r >> 7, o = r & 127;
        const float* W = which ? pWq : gWq;
        d_wq4[which * 4096 + k4 * 128 + o] =
            *reinterpret_cast<const float4*>(W + o * 128 + (k4 << 2));
    }
}

// ---------------------------------------------------------------------------
// Precompute P[b][l][o] = Wih·emb[l][b] + (bih+bhh)[o]  and P0 from decoder.
// grid = 2048 (b), 512 threads (o). Uses d_wt4 rows 0..31 (transposed Wih).
// ---------------------------------------------------------------------------
__global__ void __launch_bounds__(512) ptrnet_preP(
    const float* __restrict__ emb, const float* __restrict__ dec,
    const float* __restrict__ bih, const float* __restrict__ bhh)
{
    __shared__ float xs[Lsz * Esz];   // 32KB
    __shared__ float ds[Esz];
    const int b = blockIdx.x, o = threadIdx.x;

    for (int idx = o; idx < Lsz * Esz; idx += 512) {
        int l = idx >> 7, e = idx & 127;
        xs[idx] = emb[((size_t)l * Bsz + b) * Esz + e];
    }
    if (o < Esz) ds[o] = dec[(size_t)b * Esz + o];
    __syncthreads();

    const float bt = bih[o] + bhh[o];

    // P0
    {
        unsigned long long acc = pack2(bt, 0.f);
        #pragma unroll 8
        for (int kk = 0; kk < 32; kk++) {
            ulonglong2 w2 = *reinterpret_cast<const ulonglong2*>(&d_wt4[(kk << 9) + o]);
            ulonglong2 x2 = *reinterpret_cast<const ulonglong2*>(&ds[kk << 2]);
            FMA2(acc, w2.x, x2.x, acc);
            FMA2(acc, w2.y, x2.y, acc);
        }
        d_P0[(size_t)b * 512 + o] = hsum2(acc);
    }
    // P, 4 chunks of 16 l
    for (int c = 0; c < 4; c++) {
        unsigned long long acc[16];
        #pragma unroll
        for (int j = 0; j < 16; j++) acc[j] = pack2(bt, 0.f);
        #pragma unroll 2
        for (int kk = 0; kk < 32; kk++) {
            ulonglong2 w2 = *reinterpret_cast<const ulonglong2*>(&d_wt4[(kk << 9) + o]);
            #pragma unroll
            for (int j = 0; j < 16; j++) {
                ulonglong2 x2 = *reinterpret_cast<const ulonglong2*>(
                    &xs[(((c << 4) + j) << 7) + (kk << 2)]);
                FMA2(acc[j], w2.x, x2.x, acc[j]);
                FMA2(acc[j], w2.y, x2.y, acc[j]);
            }
        }
        #pragma unroll
        for (int j = 0; j < 16; j++)
            d_P[(((size_t)b << 6) + (c << 4) + j) * 512 + o] = hsum2(acc[j]);
    }
}

// ---------------------------------------------------------------------------
// Precompute e_g/e_p
// ---------------------------------------------------------------------------
__global__ void __launch_bounds__(128) ptrnet_pre(
    const float* __restrict__ ctx,
    const float* __restrict__ gWref, const float* __restrict__ gbref,
    const float* __restrict__ pWref, const float* __restrict__ pbref)
{
    __shared__ float cs[Lsz * Hsz];
    const int b = blockIdx.x, t = threadIdx.x;
    for (int l = 0; l < Lsz; l++)
        cs[l * Hsz + t] = ctx[((size_t)l * Bsz + b) * Hsz + t];
    __syncthreads();

    {
        float acc[Lsz];
        #pragma unroll
        for (int l = 0; l < Lsz; l++) acc[l] = 0.f;
        const float4* wr = reinterpret_cast<const float4*>(gWref + t * Hsz);
        #pragma unroll 1
        for (int k4 = 0; k4 < 32; k4++) {
            float4 w = wr[k4];
            #pragma unroll
            for (int l = 0; l < Lsz; l++) {
                float4 c = *reinterpret_cast<const float4*>(&cs[l * Hsz + k4 * 4]);
                acc[l] += w.x * c.x + w.y * c.y + w.z * c.z + w.w * c.w;
            }
        }
        float bias = gbref[t];
        #pragma unroll
        for (int l = 0; l < Lsz; l++)
            d_eg[((size_t)b * Lsz + l) * Hsz + t] = acc[l] + bias;
    }
    {
        float acc[Lsz];
        #pragma unroll
        for (int l = 0; l < Lsz; l++) acc[l] = 0.f;
        const float4* wr = reinterpret_cast<const float4*>(pWref + t * Hsz);
        #pragma unroll 1
        for (int k4 = 0; k4 < 32; k4++) {
            float4 w = wr[k4];
            #pragma unroll
            for (int l = 0; l < Lsz; l++) {
                float4 c = *reinterpret_cast<const float4*>(&cs[l * Hsz + k4 * 4]);
                acc[l] += w.x * c.x + w.y * c.y + w.z * c.z + w.w * c.w;
            }
        }
        float bias = pbref[t];
        #pragma unroll
        for (int l = 0; l < Lsz; l++)
            d_ep[((size_t)b * Lsz + l) * Hsz + t] = acc[l] + bias;
    }
}

// ---------------------------------------------------------------------------
// Persistent decode kernel: phase A = Whh·h only (Wih·x preapplied via P),
// Wq in smem, masked-work compaction, terminal early-exit.
// smem float offsets:
// ---------------------------------------------------------------------------
#define OWQ  0                     // transposed gWq|pWq as float4: 32768 floats
#define OXH  32768                 // [BM][128] h                  1792
#define OG   34560                 // [BM][512] gates half0        7168
#define OG2  41728                 // [BM][512] gates half1        7168
#define OC   48896                 // [BM][128]                    1792
#define OQ   50688                 // [BM][128] qg / qp            1792
#define OGL  52480                 // [BM][128] glimpse            1792
#define OU   54272                 // [BM][64]                     896
#define OS   55168                 // [BM][64]                     896
#define OGBQ 56064
#define OPBQ 56192
#define OGV  56320
#define OPV  56448
#define SMEM_FLOATS 56576          // 226304 bytes

__global__ void __launch_bounds__(NT, 1) ptrnet_main(
    const float* __restrict__ h0,  const float* __restrict__ c0,
    const float* __restrict__ gbq, const float* __restrict__ pbq,
    const float* __restrict__ gv,  const float* __restrict__ pv,
    float* __restrict__ out)
{
    extern __shared__ float s[];
    __shared__ unsigned long long mask_s[BM];
    __shared__ int idx_s[BM];
    __shared__ int bb_s[BM];
    __shared__ int cnt_s[BM];
    __shared__ int off_s[BM];
    __shared__ int R_s;
    __shared__ unsigned short rowlist[BM * Lsz];

    const int tid = threadIdx.x;
    const int bid = blockIdx.x;

    // ---- prologue ----
    {   // Wq -> smem (float4 copy, coalesced)
        float4* s4 = reinterpret_cast<float4*>(&s[OWQ]);
        for (int i = tid; i < 8192; i += NT) s4[i] = d_wq4[i];
    }
    if (tid < 128) {
        s[OGBQ + tid] = gbq[tid];  s[OPBQ + tid] = pbq[tid];
        s[OGV + tid]  = gv[tid];   s[OPV + tid]  = pv[tid];
    }
    for (int i = tid; i < BM * Hsz; i += NT) {
        int m = i >> 7, j = i & 127;
        int bb = min(bid * BM + m, Bsz - 1);
        s[OXH + m * 128 + j] = h0[bb * Hsz + j];
        s[OC  + m * 128 + j] = c0[bb * Hsz + j];
    }
    if (tid < BM) {
        mask_s[tid] = 0ull; idx_s[tid] = 0;
        bb_s[tid] = min(bid * BM + tid, Bsz - 1);
    }
    for (int i = tid; i < BM * Lsz; i += NT) {
        int m = i >> 6, l = i & 63;
        int b = bid * BM + m;
        if (b < Bsz) out[(size_t)b * Lsz + l] = (l == 0) ? 1.0f : 0.0f;
    }
    __syncthreads();

    const int warp = tid >> 5, lane = tid & 31;
    const int grp = lane >> 3, lk = lane & 7;
    const int o512 = tid & 511, hf = tid >> 9;
    const int o128 = tid & 127, mg8 = tid >> 7;

    for (int step = 0; step < NSTEPS; step++) {
        // ---- preload P rows for phase B (no dependency on phase A) ----
        float pA0[2], pA1[2], pA2[2], pA3[2];
        #pragma unroll
        for (int it = 0; it < 2; it++) {
            int i = tid + it * NT;
            if (i < BM * Hsz) {
                int m = i >> 7, j = i & 127;
                const float* pr = (step == 0)
                    ? (d_P0 + (size_t)bb_s[m] * 512)
                    : (d_P + (((size_t)bb_s[m] << 6) + idx_s[m]) * 512);
                pA0[it] = pr[j];       pA1[it] = pr[128 + j];
                pA2[it] = pr[256 + j]; pA3[it] = pr[384 + j];
            }
        }

        // ---- mask update + per-row unmasked count ----
        if (tid < BM) {
            unsigned long long mk = mask_s[tid] | (1ull << idx_s[tid]);
            if (idx_s[tid] != 0) mk &= ~1ull;
            mask_s[tid] = mk;
            cnt_s[tid] = 64 - __popcll(mk);
        }

        // ---- phase A: Whh·h split-K (K=128 -> 64 per half) ----
        {
            unsigned long long acc[BM];
            #pragma unroll
            for (int m = 0; m < BM; m++) acc[m] = pack2(0.f, 0.f);
            const int k4base = 32 + (hf << 4);   // Whh rows of d_wt4
            const int xoff = hf << 6;
            #pragma unroll 8
            for (int kk = 0; kk < 16; kk++) {
                const ulonglong2 w2 = *reinterpret_cast<const ulonglong2*>(
                    &d_wt4[((k4base + kk) << 9) + o512]);
                #pragma unroll
                for (int m = 0; m < BM; m++) {
                    const ulonglong2 x2 = *reinterpret_cast<const ulonglong2*>(
                        &s[OXH + m * 128 + xoff + (kk << 2)]);
                    FMA2(acc[m], w2.x, x2.x, acc[m]);
                    FMA2(acc[m], w2.y, x2.y, acc[m]);
                }
            }
            const int og = hf ? OG2 : OG;
            #pragma unroll
            for (int m = 0; m < BM; m++) s[og + m * 512 + o512] = hsum2(acc[m]);
        }
        __syncthreads();

        // ---- phase B: gates = OG + OG2 + P; LSTM pointwise; rowlist ----
        #pragma unroll
        for (int it = 0; it < 2; it++) {
            int i = tid + it * NT;
            if (i < BM * Hsz) {
                int m = i >> 7, j = i & 127;
                float ig = fsigm(s[OG + m * 512 + j]       + s[OG2 + m * 512 + j]       + pA0[it]);
                float fg = fsigm(s[OG + m * 512 + 128 + j] + s[OG2 + m * 512 + 128 + j] + pA1[it]);
                float gg = ftanh(s[OG + m * 512 + 256 + j] + s[OG2 + m * 512 + 256 + j] + pA2[it]);
                float og = fsigm(s[OG + m * 512 + 384 + j] + s[OG2 + m * 512 + 384 + j] + pA3[it]);
                float cn = fg * s[OC + m * 128 + j] + ig * gg;
                s[OC + m * 128 + j] = cn;
                s[OXH + m * 128 + j] = og * ftanh(cn);   // h_new
            }
        }
        if (tid < BM) {
            int off = 0;
            for (int j = 0; j < tid; j++) off += cnt_s[j];
            off_s[tid] = off;
            unsigned long long unm = ~mask_s[tid];
            int k = 0;
            while (unm) {
                int l = __ffsll((long long)unm) - 1;
                rowlist[off + k] = (unsigned short)((tid << 6) | l);
                k++;
                unm &= unm - 1;
            }
        }
        if (tid == 0) {
            int R = 0;
            #pragma unroll
            for (int j = 0; j < BM; j++) R += cnt_s[j];
            R_s = R;
        }
        __syncthreads();

        const int Rv = R_s;
        const int nIter = (Rv + 127) >> 7;

        // ---- terminal state: outputs uniform 1/64 forever. Burst + exit ----
        if (Rv == 0) {
            const float u = 0.015625f;
            for (int st = step + 1; st <= NSTEPS; st++) {
                float* orow = out + (size_t)st * Bsz * Lsz;
                for (int i = tid; i < BM * Lsz; i += NT) {
                    int m = i >> 6;
                    int b = bid * BM + m;
                    if (b < Bsz) orow[(size_t)b * Lsz + (i & 63)] = u;
                }
            }
            return;
        }

        // ---- qg[m][o] = gWq[o]·h_new[m] + gbq[o]  (Wq from smem) ----
        {
            for (int m = mg8; m < BM; m += 8) {
                unsigned long long a2 = pack2(s[OGBQ + o128], 0.f);
                #pragma unroll 8
                for (int k4 = 0; k4 < 32; k4++) {
                    ulonglong2 w2 = *reinterpret_cast<const ulonglong2*>(
                        &s[OWQ + (((k4 << 7) + o128) << 2)]);
                    ulonglong2 h2 = *reinterpret_cast<const ulonglong2*>(
                        &s[OXH + m * 128 + (k4 << 2)]);
                    FMA2(a2, w2.x, h2.x, a2);
                    FMA2(a2, w2.y, h2.y, a2);
                }
                s[OQ + m * 128 + o128] = hsum2(a2);
            }
        }
        __syncthreads();

        // ---- ug: only unmasked rows (uniform trip count) ----
        for (int k = 0; k < nIter; k++) {
            int r = warp * 4 + grp + (k << 7);
            bool valid = (r < Rv);
            int e = rowlist[valid ? r : 0];
            int m = e >> 6, l = e & 63;
            const float4* e4 = reinterpret_cast<const float4*>(
                d_eg + ((size_t)bb_s[m] * Lsz + l) * Hsz);
            float acc = 0.f;
            #pragma unroll
            for (int j = 0; j < 4; j++) {
                int k4 = (j << 3) + lk;
                float4 ev = e4[k4];
                float4 q = *reinterpret_cast<const float4*>(&s[OQ + m * 128 + (k4 << 2)]);
                float4 g = *reinterpret_cast<const float4*>(&s[OGV + (k4 << 2)]);
                acc += g.x * ftanh(q.x + ev.x) + g.y * ftanh(q.y + ev.y)
                     + g.z * ftanh(q.z + ev.z) + g.w * ftanh(q.w + ev.w);
            }
            acc += __shfl_xor_sync(0xffffffffu, acc, 1);
            acc += __shfl_xor_sync(0xffffffffu, acc, 2);
            acc += __shfl_xor_sync(0xffffffffu, acc, 4);
            if (valid && lk == 0) s[OU + (m << 6) + l] = acc;
        }
        __syncthreads();

        // ---- glimpse softmax (masked) ----
        if (warp < BM) {
            int m = warp;
            unsigned long long mk = mask_s[m];
            float v0 = ((mk >> lane) & 1ull)        ? NEGV : s[OU + m * 64 + lane];
            float v1 = ((mk >> (lane + 32)) & 1ull) ? NEGV : s[OU + m * 64 + 32 + lane];
            float mx = fmaxf(v0, v1);
            for (int off = 16; off; off >>= 1)
                mx = fmaxf(mx, __shfl_xor_sync(0xffffffffu, mx, off));
            float e0 = __expf(v0 - mx), e1 = __expf(v1 - mx);
            float sum = e0 + e1;
            for (int off = 16; off; off >>= 1)
                sum += __shfl_xor_sync(0xffffffffu, sum, off);
            float inv = __fdividef(1.f, sum);
            s[OS + m * 64 + lane]      = e0 * inv;
            s[OS + m * 64 + 32 + lane] = e1 * inv;
        }
        __syncthreads();

        // ---- g_l[m][h] = sum_l e_g[b][l][h] * sm[m][l] (skip sm==0) ----
        {
            for (int m = mg8; m < BM; m += 8) {
                const float* eg = d_eg + ((size_t)bb_s[m] * Lsz) * Hsz + o128;
                float acc = 0.f;
                int off = off_s[m], cn = cnt_s[m];
                for (int j = 0; j < cn; j++) {
                    int l = rowlist[off + j] & 63;
                    acc += eg[(size_t)l * Hsz] * s[OS + m * 64 + l];
                }
                s[OGL + m * 128 + o128] = acc;
            }
        }
        __syncthreads();

        // ---- qp[m][o] = pWq[o]·g_l[m] + pbq[o]  (Wq from smem) ----
        {
            for (int m = mg8; m < BM; m += 8) {
                unsigned long long a2 = pack2(s[OPBQ + o128], 0.f);
                #pragma unroll 8
                for (int k4 = 0; k4 < 32; k4++) {
                    ulonglong2 w2 = *reinterpret_cast<const ulonglong2*>(
                        &s[OWQ + ((4096 + (k4 << 7) + o128) << 2)]);
                    ulonglong2 g2 = *reinterpret_cast<const ulonglong2*>(
                        &s[OGL + m * 128 + (k4 << 2)]);
                    FMA2(a2, w2.x, g2.x, a2);
                    FMA2(a2, w2.y, g2.y, a2);
                }
                s[OQ + m * 128 + o128] = hsum2(a2);
            }
        }
        __syncthreads();

        // ---- up: only unmasked rows (uniform trip count) ----
        for (int k = 0; k < nIter; k++) {
            int r = warp * 4 + grp + (k << 7);
            bool valid = (r < Rv);
            int e = rowlist[valid ? r : 0];
            int m = e >> 6, l = e & 63;
            const float4* e4 = reinterpret_cast<const float4*>(
                d_ep + ((size_t)bb_s[m] * Lsz + l) * Hsz);
            float acc = 0.f;
            #pragma unroll
            for (int j = 0; j < 4; j++) {
                int k4 = (j << 3) + lk;
                float4 ev = e4[k4];
                float4 q = *reinterpret_cast<const float4*>(&s[OQ + m * 128 + (k4 << 2)]);
                float4 p = *reinterpret_cast<const float4*>(&s[OPV + (k4 << 2)]);
                acc += p.x * ftanh(q.x + ev.x) + p.y * ftanh(q.y + ev.y)
                     + p.z * ftanh(q.z + ev.z) + p.w * ftanh(q.w + ev.w);
            }
            acc += __shfl_xor_sync(0xffffffffu, acc, 1);
            acc += __shfl_xor_sync(0xffffffffu, acc, 2);
            acc += __shfl_xor_sync(0xffffffffu, acc, 4);
            if (valid && lk == 0) s[OU + (m << 6) + l] = acc;
        }
        __syncthreads();

        // ---- pointer: 10*tanh, mask, softmax, argmax, write probs ----
        if (warp < BM) {
            int m = warp;
            unsigned long long mk = mask_s[m];
            float r0 = 10.f * tanhf(s[OU + m * 64 + lane]);
            float r1 = 10.f * tanhf(s[OU + m * 64 + 32 + lane]);
            float v0 = ((mk >> lane) & 1ull)        ? NEGV : r0;
            float v1 = ((mk >> (lane + 32)) & 1ull) ? NEGV : r1;
            float mv; int mi;
            if (v0 >= v1) { mv = v0; mi = lane; } else { mv = v1; mi = lane + 32; }
            for (int off = 16; off; off >>= 1) {
                float ov = __shfl_xor_sync(0xffffffffu, mv, off);
                int   oi = __shfl_xor_sync(0xffffffffu, mi, off);
                if (ov > mv || (ov == mv && oi < mi)) { mv = ov; mi = oi; }
            }
            float e0 = __expf(v0 - mv), e1 = __expf(v1 - mv);
            float sum = e0 + e1;
            for (int off = 16; off; off >>= 1)
                sum += __shfl_xor_sync(0xffffffffu, sum, off);
            float inv = __fdividef(1.f, sum);
            int b = bid * BM + m;
            if (b < Bsz) {
                float* op = out + ((size_t)(step + 1) * Bsz + b) * Lsz;
                op[lane]      = e0 * inv;
                op[lane + 32] = e1 * inv;
            }
            if (lane == 0) idx_s[m] = mi;
        }
        __syncthreads();   // idx_s visible for next step's preload + mask update
    }
}

extern "C" void kernel_launch(void* const* d_in, const int* in_sizes, int n_in,
                              void* d_out, int out_size)
{
    const float* dec   = (const float*)d_in[0];
    const float* emb   = (const float*)d_in[1];
    const float* ctx   = (const float*)d_in[2];
    const float* h0    = (const float*)d_in[3];
    const float* c0    = (const float*)d_in[4];
    const float* Wih   = (const float*)d_in[5];
    const float* Whh   = (const float*)d_in[6];
    const float* bih   = (const float*)d_in[7];
    const float* bhh   = (const float*)d_in[8];
    const float* gWq   = (const float*)d_in[9];
    const float* gbq   = (const float*)d_in[10];
    const float* gWref = (const float*)d_in[11];
    const float* gbref = (const float*)d_in[12];
    const float* gv    = (const float*)d_in[13];
    const float* pWq   = (const float*)d_in[14];
    const float* pbq   = (const float*)d_in[15];
    const float* pWref = (const float*)d_in[16];
    const float* pbref = (const float*)d_in[17];
    const float* pv    = (const float*)d_in[18];
    float* out = (float*)d_out;

    cudaFuncSetAttribute(ptrnet_main, cudaFuncAttributeMaxDynamicSharedMemorySize,
                         SMEM_FLOATS * 4);

    ptrnet_prew<<<80, 512>>>(Wih, Whh, gWq, pWq);
    ptrnet_preP<<<Bsz, 512>>>(emb, dec, bih, bhh);
    ptrnet_pre<<<Bsz, 128>>>(ctx, gWref, gbref, pWref, pbref);
    ptrnet_main<<<GRID, NT, SMEM_FLOATS * 4>>>(h0, c0, gbq, pbq, gv, pv, out);
}

// round 9
// speedup vs baseline: 2.2079x; 1.0828x over previous
#include <cuda_runtime.h>
#include <math.h>

#define Bsz 2048
#define Lsz 64
#define Esz 128
#define Hsz 128
#define NSTEPS 126
#define BM 14
#define NT 1024
#define GRID 147               // ceil(2048/14)
#define NEGV -1000000000.0f

// scratch (module-static device arrays: allowed)
__device__ float d_eg[(size_t)Bsz * Lsz * Hsz];   // e_g[b][l][h]
__device__ float d_ep[(size_t)Bsz * Lsz * Hsz];   // e_p[b][l][h]
__device__ float4 d_wt4[64 * 512];                // transposed LSTM weights [k4][o] (Wih 0..31, Whh 32..63)
__device__ float4 d_wq4[2 * 32 * 128];            // transposed gWq|pWq [which][k4][o]
__device__ float  d_P[(size_t)Bsz * Lsz * 512];   // P[b][l][o] = Wih·emb[l,b] + bt
__device__ float  d_P0[(size_t)Bsz * 512];        // P0[b][o]   = Wih·dec[b] + bt

// packed f32x2 FMA (Blackwell): d = a*b + c elementwise, IEEE rn per lane
#define FMA2(d, a, b, c) \
    asm("fma.rn.f32x2 %0, %1, %2, %3;" : "=l"(d) : "l"(a), "l"(b), "l"(c))

__device__ __forceinline__ unsigned long long pack2(float lo, float hi) {
    unsigned long long r;
    asm("mov.b64 %0, {%1, %2};" : "=l"(r) : "f"(lo), "f"(hi));
    return r;
}
__device__ __forceinline__ float hsum2(unsigned long long v) {
    float a, b;
    asm("mov.b64 {%0, %1}, %2;" : "=f"(a), "=f"(b) : "l"(v));
    return a + b;
}

__device__ __forceinline__ float ftanh(float x) {
    float e = __expf(2.f * x);
    return 1.f - __fdividef(2.f, e + 1.f);
}
__device__ __forceinline__ float fsigm(float x) {
    return __fdividef(1.f, 1.f + __expf(-x));
}

// ---------------------------------------------------------------------------
// Transpose LSTM weights + Wq matrices into coalesced [k][o] layouts
// ---------------------------------------------------------------------------
__global__ void __launch_bounds__(512) ptrnet_prew(
    const float* __restrict__ Wih, const float* __restrict__ Whh,
    const float* __restrict__ gWq, const float* __restrict__ pWq)
{
    int i = blockIdx.x * blockDim.x + threadIdx.x;
    if (i < 64 * 512) {
        int k4 = i >> 9, o = i & 511;
        const float* src = (k4 < 32) ? (Wih + o * 128 + (k4 << 2))
                                     : (Whh + o * 128 + ((k4 - 32) << 2));
        d_wt4[i] = *reinterpret_cast<const float4*>(src);
    } else if (i < 64 * 512 + 2 * 4096) {
        int j = i - 64 * 512;
        int which = j >> 12, r = j & 4095;
        int k4 = r >> 7, o = r & 127;
        const float* W = which ? pWq : gWq;
        d_wq4[which * 4096 + k4 * 128 + o] =
            *reinterpret_cast<const float4*>(W + o * 128 + (k4 << 2));
    }
}

// ---------------------------------------------------------------------------
// Precompute P[b][l][o] = Wih·emb[l][b] + (bih+bhh)[o]  and P0 from decoder.
// ---------------------------------------------------------------------------
__global__ void __launch_bounds__(512) ptrnet_preP(
    const float* __restrict__ emb, const float* __restrict__ dec,
    const float* __restrict__ bih, const float* __restrict__ bhh)
{
    __shared__ float xs[Lsz * Esz];   // 32KB
    __shared__ float ds[Esz];
    const int b = blockIdx.x, o = threadIdx.x;

    for (int idx = o; idx < Lsz * Esz; idx += 512) {
        int l = idx >> 7, e = idx & 127;
        xs[idx] = emb[((size_t)l * Bsz + b) * Esz + e];
    }
    if (o < Esz) ds[o] = dec[(size_t)b * Esz + o];
    __syncthreads();

    const float bt = bih[o] + bhh[o];

    {   // P0
        unsigned long long acc = pack2(bt, 0.f);
        #pragma unroll 8
        for (int kk = 0; kk < 32; kk++) {
            ulonglong2 w2 = *reinterpret_cast<const ulonglong2*>(&d_wt4[(kk << 9) + o]);
            ulonglong2 x2 = *reinterpret_cast<const ulonglong2*>(&ds[kk << 2]);
            FMA2(acc, w2.x, x2.x, acc);
            FMA2(acc, w2.y, x2.y, acc);
        }
        d_P0[(size_t)b * 512 + o] = hsum2(acc);
    }
    for (int c = 0; c < 4; c++) {
        unsigned long long acc[16];
        #pragma unroll
        for (int j = 0; j < 16; j++) acc[j] = pack2(bt, 0.f);
        #pragma unroll 2
        for (int kk = 0; kk < 32; kk++) {
            ulonglong2 w2 = *reinterpret_cast<const ulonglong2*>(&d_wt4[(kk << 9) + o]);
            #pragma unroll
            for (int j = 0; j < 16; j++) {
                ulonglong2 x2 = *reinterpret_cast<const ulonglong2*>(
                    &xs[(((c << 4) + j) << 7) + (kk << 2)]);
                FMA2(acc[j], w2.x, x2.x, acc[j]);
                FMA2(acc[j], w2.y, x2.y, acc[j]);
            }
        }
        #pragma unroll
        for (int j = 0; j < 16; j++)
            d_P[(((size_t)b << 6) + (c << 4) + j) * 512 + o] = hsum2(acc[j]);
    }
}

// ---------------------------------------------------------------------------
// Precompute e_g/e_p
// ---------------------------------------------------------------------------
__global__ void __launch_bounds__(128) ptrnet_pre(
    const float* __restrict__ ctx,
    const float* __restrict__ gWref, const float* __restrict__ gbref,
    const float* __restrict__ pWref, const float* __restrict__ pbref)
{
    __shared__ float cs[Lsz * Hsz];
    const int b = blockIdx.x, t = threadIdx.x;
    for (int l = 0; l < Lsz; l++)
        cs[l * Hsz + t] = ctx[((size_t)l * Bsz + b) * Hsz + t];
    __syncthreads();

    {
        float acc[Lsz];
        #pragma unroll
        for (int l = 0; l < Lsz; l++) acc[l] = 0.f;
        const float4* wr = reinterpret_cast<const float4*>(gWref + t * Hsz);
        #pragma unroll 1
        for (int k4 = 0; k4 < 32; k4++) {
            float4 w = wr[k4];
            #pragma unroll
            for (int l = 0; l < Lsz; l++) {
                float4 c = *reinterpret_cast<const float4*>(&cs[l * Hsz + k4 * 4]);
                acc[l] += w.x * c.x + w.y * c.y + w.z * c.z + w.w * c.w;
            }
        }
        float bias = gbref[t];
        #pragma unroll
        for (int l = 0; l < Lsz; l++)
            d_eg[((size_t)b * Lsz + l) * Hsz + t] = acc[l] + bias;
    }
    {
        float acc[Lsz];
        #pragma unroll
        for (int l = 0; l < Lsz; l++) acc[l] = 0.f;
        const float4* wr = reinterpret_cast<const float4*>(pWref + t * Hsz);
        #pragma unroll 1
        for (int k4 = 0; k4 < 32; k4++) {
            float4 w = wr[k4];
            #pragma unroll
            for (int l = 0; l < Lsz; l++) {
                float4 c = *reinterpret_cast<const float4*>(&cs[l * Hsz + k4 * 4]);
                acc[l] += w.x * c.x + w.y * c.y + w.z * c.z + w.w * c.w;
            }
        }
        float bias = pbref[t];
        #pragma unroll
        for (int l = 0; l < Lsz; l++)
            d_ep[((size_t)b * Lsz + l) * Hsz + t] = acc[l] + bias;
    }
}

// ---------------------------------------------------------------------------
// Persistent decode kernel
// smem float offsets:
// ---------------------------------------------------------------------------
#define OWQ  0                     // transposed gWq|pWq as float4: 32768 floats
#define OXH  32768                 // [BM][128] h                  1792
#define OG   34560                 // [BM][512] gates half0 / qg-qp partials [4][14][128]
#define OG2  41728                 // [BM][512] gates half1        7168
#define OC   48896                 // [BM][128]                    1792
#define OQ   50688                 // [BM][128] qg / qp            1792
#define OGL  52480                 // [BM][128] glimpse            1792
#define OU   54272                 // [BM][64]                     896
#define OS   55168                 // [BM][64]                     896
#define OGBQ 56064
#define OPBQ 56192
#define OGV  56320
#define OPV  56448
#define SMEM_FLOATS 56576          // 226304 bytes

__global__ void __launch_bounds__(NT, 1) ptrnet_main(
    const float* __restrict__ h0,  const float* __restrict__ c0,
    const float* __restrict__ gbq, const float* __restrict__ pbq,
    const float* __restrict__ gv,  const float* __restrict__ pv,
    float* __restrict__ out)
{
    extern __shared__ float s[];
    __shared__ unsigned long long mask_s[BM];
    __shared__ int idx_s[BM];
    __shared__ int bb_s[BM];
    __shared__ int cnt_s[BM];
    __shared__ int off_s[BM];
    __shared__ int R_s;
    __shared__ unsigned short rowlist[BM * Lsz];

    const int tid = threadIdx.x;
    const int bid = blockIdx.x;

    // ---- prologue ----
    {
        float4* s4 = reinterpret_cast<float4*>(&s[OWQ]);
        for (int i = tid; i < 8192; i += NT) s4[i] = d_wq4[i];
    }
    if (tid < 128) {
        s[OGBQ + tid] = gbq[tid];  s[OPBQ + tid] = pbq[tid];
        s[OGV + tid]  = gv[tid];   s[OPV + tid]  = pv[tid];
    }
    for (int i = tid; i < BM * Hsz; i += NT) {
        int m = i >> 7, j = i & 127;
        int bb = min(bid * BM + m, Bsz - 1);
        s[OXH + m * 128 + j] = h0[bb * Hsz + j];
        s[OC  + m * 128 + j] = c0[bb * Hsz + j];
    }
    if (tid < BM) {
        mask_s[tid] = 0ull; idx_s[tid] = 0;
        bb_s[tid] = min(bid * BM + tid, Bsz - 1);
    }
    for (int i = tid; i < BM * Lsz; i += NT) {
        int m = i >> 6, l = i & 63;
        int b = bid * BM + m;
        if (b < Bsz) out[(size_t)b * Lsz + l] = (l == 0) ? 1.0f : 0.0f;
    }
    __syncthreads();

    const int warp = tid >> 5, lane = tid & 31;
    const int grp = lane >> 3, lk = lane & 7;
    const int o512 = tid & 511, hf = tid >> 9;
    const int o128 = tid & 127;
    const int kq = tid >> 8;            // 0..3 (qg/qp split-K slice)
    const int mv = (tid >> 7) & 1;      // 0..1
    const int mbase = mv * 7;           // m 0..6 or 7..13

    // hoisted attention vectors
    float4 gvr[4], pvr[4];
    #pragma unroll
    for (int j = 0; j < 4; j++) {
        gvr[j] = *reinterpret_cast<const float4*>(&s[OGV + (((j << 3) + lk) << 2)]);
        pvr[j] = *reinterpret_cast<const float4*>(&s[OPV + (((j << 3) + lk) << 2)]);
    }

    for (int step = 0; step < NSTEPS; step++) {
        // ---- preload P rows for phase B ----
        float pA0[2], pA1[2], pA2[2], pA3[2];
        #pragma unroll
        for (int it = 0; it < 2; it++) {
            int i = tid + it * NT;
            if (i < BM * Hsz) {
                int m = i >> 7, j = i & 127;
                const float* pr = (step == 0)
                    ? (d_P0 + (size_t)bb_s[m] * 512)
                    : (d_P + (((size_t)bb_s[m] << 6) + idx_s[m]) * 512);
                pA0[it] = pr[j];       pA1[it] = pr[128 + j];
                pA2[it] = pr[256 + j]; pA3[it] = pr[384 + j];
            }
        }

        // ---- mask update ----
        if (tid < BM) {
            unsigned long long mk = mask_s[tid] | (1ull << idx_s[tid]);
            if (idx_s[tid] != 0) mk &= ~1ull;
            mask_s[tid] = mk;
            cnt_s[tid] = 64 - __popcll(mk);
        }

        // ---- phase A: Whh·h split-K ----
        {
            unsigned long long acc[BM];
            #pragma unroll
            for (int m = 0; m < BM; m++) acc[m] = pack2(0.f, 0.f);
            const int k4base = 32 + (hf << 4);
            const int xoff = hf << 6;
            #pragma unroll 8
            for (int kk = 0; kk < 16; kk++) {
                const ulonglong2 w2 = *reinterpret_cast<const ulonglong2*>(
                    &d_wt4[((k4base + kk) << 9) + o512]);
                #pragma unroll
                for (int m = 0; m < BM; m++) {
                    const ulonglong2 x2 = *reinterpret_cast<const ulonglong2*>(
                        &s[OXH + m * 128 + xoff + (kk << 2)]);
                    FMA2(acc[m], w2.x, x2.x, acc[m]);
                    FMA2(acc[m], w2.y, x2.y, acc[m]);
                }
            }
            const int og = hf ? OG2 : OG;
            #pragma unroll
            for (int m = 0; m < BM; m++) s[og + m * 512 + o512] = hsum2(acc[m]);
        }
        __syncthreads();

        // ---- phase B: gates + LSTM pointwise + rowlist ----
        #pragma unroll
        for (int it = 0; it < 2; it++) {
            int i = tid + it * NT;
            if (i < BM * Hsz) {
                int m = i >> 7, j = i & 127;
                float ig = fsigm(s[OG + m * 512 + j]       + s[OG2 + m * 512 + j]       + pA0[it]);
                float fg = fsigm(s[OG + m * 512 + 128 + j] + s[OG2 + m * 512 + 128 + j] + pA1[it]);
                float gg = ftanh(s[OG + m * 512 + 256 + j] + s[OG2 + m * 512 + 256 + j] + pA2[it]);
                float og = fsigm(s[OG + m * 512 + 384 + j] + s[OG2 + m * 512 + 384 + j] + pA3[it]);
                float cn = fg * s[OC + m * 128 + j] + ig * gg;
                s[OC + m * 128 + j] = cn;
                s[OXH + m * 128 + j] = og * ftanh(cn);
            }
        }
        if (tid < BM) {
            int off = 0;
            for (int j = 0; j < tid; j++) off += cnt_s[j];
            off_s[tid] = off;
            unsigned long long unm = ~mask_s[tid];
            int k = 0;
            while (unm) {
                int l = __ffsll((long long)unm) - 1;
                rowlist[off + k] = (unsigned short)((tid << 6) | l);
                k++;
                unm &= unm - 1;
            }
        }
        if (tid == 0) {
            int R = 0;
            #pragma unroll
            for (int j = 0; j < BM; j++) R += cnt_s[j];
            R_s = R;
        }
        __syncthreads();

        const int Rv = R_s;
        const int nIter = (Rv + 127) >> 7;

        // ---- terminal state: burst uniform 1/64 + exit ----
        if (Rv == 0) {
            const float u = 0.015625f;
            for (int st = step + 1; st <= NSTEPS; st++) {
                float* orow = out + (size_t)st * Bsz * Lsz;
                for (int i = tid; i < BM * Lsz; i += NT) {
                    int m = i >> 6;
                    int b = bid * BM + m;
                    if (b < Bsz) orow[(size_t)b * Lsz + (i & 63)] = u;
                }
            }
            return;
        }

        // ---- qg partials: thread (kq, mv, o128) does 7 m over 8 k4 ----
        {
            unsigned long long acc[7];
            #pragma unroll
            for (int j = 0; j < 7; j++) acc[j] = pack2(0.f, 0.f);
            #pragma unroll
            for (int kk = 0; kk < 8; kk++) {
                const int k4 = (kq << 3) + kk;
                ulonglong2 w2 = *reinterpret_cast<const ulonglong2*>(
                    &s[OWQ + (((k4 << 7) + o128) << 2)]);
                #pragma unroll
                for (int j = 0; j < 7; j++) {
                    ulonglong2 h2 = *reinterpret_cast<const ulonglong2*>(
                        &s[OXH + (mbase + j) * 128 + (k4 << 2)]);
                    FMA2(acc[j], w2.x, h2.x, acc[j]);
                    FMA2(acc[j], w2.y, h2.y, acc[j]);
                }
            }
            #pragma unroll
            for (int j = 0; j < 7; j++)
                s[OG + ((kq * 14 + mbase + j) << 7) + o128] = hsum2(acc[j]);
        }
        __syncthreads();

        // ---- qg reduce (FIXED: strided over all BM*128 = 1792 entries) ----
        for (int i = tid; i < BM * 128; i += NT) {
            int m = i >> 7, o = i & 127;
            float q = ((s[OG + ((m) << 7) + o]       + s[OG + ((14 + m) << 7) + o])
                     + (s[OG + ((28 + m) << 7) + o]  + s[OG + ((42 + m) << 7) + o]))
                     + s[OGBQ + o];
            s[OQ + (m << 7) + o] = q;
        }
        __syncthreads();

        // ---- ug: only unmasked rows ----
        for (int k = 0; k < nIter; k++) {
            int r = warp * 4 + grp + (k << 7);
            bool valid = (r < Rv);
            int e = rowlist[valid ? r : 0];
            int m = e >> 6, l = e & 63;
            const float4* e4 = reinterpret_cast<const float4*>(
                d_eg + ((size_t)bb_s[m] * Lsz + l) * Hsz);
            float acc = 0.f;
            #pragma unroll
            for (int j = 0; j < 4; j++) {
                int k4 = (j << 3) + lk;
                float4 ev = e4[k4];
                float4 q = *reinterpret_cast<const float4*>(&s[OQ + m * 128 + (k4 << 2)]);
                float4 g = gvr[j];
                acc += g.x * ftanh(q.x + ev.x) + g.y * ftanh(q.y + ev.y)
                     + g.z * ftanh(q.z + ev.z) + g.w * ftanh(q.w + ev.w);
            }
            acc += __shfl_xor_sync(0xffffffffu, acc, 1);
            acc += __shfl_xor_sync(0xffffffffu, acc, 2);
            acc += __shfl_xor_sync(0xffffffffu, acc, 4);
            if (valid && lk == 0) s[OU + (m << 6) + l] = acc;
        }
        __syncthreads();

        // ---- glimpse softmax (masked) ----
        if (warp < BM) {
            int m = warp;
            unsigned long long mk = mask_s[m];
            float v0 = ((mk >> lane) & 1ull)        ? NEGV : s[OU + m * 64 + lane];
            float v1 = ((mk >> (lane + 32)) & 1ull) ? NEGV : s[OU + m * 64 + 32 + lane];
            float mx = fmaxf(v0, v1);
            for (int off = 16; off; off >>= 1)
                mx = fmaxf(mx, __shfl_xor_sync(0xffffffffu, mx, off));
            float e0 = __expf(v0 - mx), e1 = __expf(v1 - mx);
            float sum = e0 + e1;
            for (int off = 16; off; off >>= 1)
                sum += __shfl_xor_sync(0xffffffffu, sum, off);
            float inv = __fdividef(1.f, sum);
            s[OS + m * 64 + lane]      = e0 * inv;
            s[OS + m * 64 + 32 + lane] = e1 * inv;
        }
        __syncthreads();

        // ---- g_l ----
        {
            const int mg8 = tid >> 7;
            for (int m = mg8; m < BM; m += 8) {
                const float* eg = d_eg + ((size_t)bb_s[m] * Lsz) * Hsz + o128;
                float acc = 0.f;
                int off = off_s[m], cn = cnt_s[m];
                for (int j = 0; j < cn; j++) {
                    int l = rowlist[off + j] & 63;
                    acc += eg[(size_t)l * Hsz] * s[OS + m * 64 + l];
                }
                s[OGL + m * 128 + o128] = acc;
            }
        }
        __syncthreads();

        // ---- qp partials ----
        {
            unsigned long long acc[7];
            #pragma unroll
            for (int j = 0; j < 7; j++) acc[j] = pack2(0.f, 0.f);
            #pragma unroll
            for (int kk = 0; kk < 8; kk++) {
                const int k4 = (kq << 3) + kk;
                ulonglong2 w2 = *reinterpret_cast<const ulonglong2*>(
                    &s[OWQ + ((4096 + (k4 << 7) + o128) << 2)]);
                #pragma unroll
                for (int j = 0; j < 7; j++) {
                    ulonglong2 g2 = *reinterpret_cast<const ulonglong2*>(
                        &s[OGL + (mbase + j) * 128 + (k4 << 2)]);
                    FMA2(acc[j], w2.x, g2.x, acc[j]);
                    FMA2(acc[j], w2.y, g2.y, acc[j]);
                }
            }
            #pragma unroll
            for (int j = 0; j < 7; j++)
                s[OG + ((kq * 14 + mbase + j) << 7) + o128] = hsum2(acc[j]);
        }
        __syncthreads();

        // ---- qp reduce (FIXED: strided over all BM*128 entries) ----
        for (int i = tid; i < BM * 128; i += NT) {
            int m = i >> 7, o = i & 127;
            float q = ((s[OG + ((m) << 7) + o]       + s[OG + ((14 + m) << 7) + o])
                     + (s[OG + ((28 + m) << 7) + o]  + s[OG + ((42 + m) << 7) + o]))
                     + s[OPBQ + o];
            s[OQ + (m << 7) + o] = q;
        }
        __syncthreads();

        // ---- up: only unmasked rows ----
        for (int k = 0; k < nIter; k++) {
            int r = warp * 4 + grp + (k << 7);
            bool valid = (r < Rv);
            int e = rowlist[valid ? r : 0];
            int m = e >> 6, l = e & 63;
            const float4* e4 = reinterpret_cast<const float4*>(
                d_ep + ((size_t)bb_s[m] * Lsz + l) * Hsz);
            float acc = 0.f;
            #pragma unroll
            for (int j = 0; j < 4; j++) {
                int k4 = (j << 3) + lk;
                float4 ev = e4[k4];
                float4 q = *reinterpret_cast<const float4*>(&s[OQ + m * 128 + (k4 << 2)]);
                float4 p = pvr[j];
                acc += p.x * ftanh(q.x + ev.x) + p.y * ftanh(q.y + ev.y)
                     + p.z * ftanh(q.z + ev.z) + p.w * ftanh(q.w + ev.w);
            }
            acc += __shfl_xor_sync(0xffffffffu, acc, 1);
            acc += __shfl_xor_sync(0xffffffffu, acc, 2);
            acc += __shfl_xor_sync(0xffffffffu, acc, 4);
            if (valid && lk == 0) s[OU + (m << 6) + l] = acc;
        }
        __syncthreads();

        // ---- pointer: 10*tanh, mask, softmax, argmax, write probs ----
        if (warp < BM) {
            int m = warp;
            unsigned long long mk = mask_s[m];
            float r0 = 10.f * tanhf(s[OU + m * 64 + lane]);
            float r1 = 10.f * tanhf(s[OU + m * 64 + 32 + lane]);
            float v0 = ((mk >> lane) & 1ull)        ? NEGV : r0;
            float v1 = ((mk >> (lane + 32)) & 1ull) ? NEGV : r1;
            float mv2; int mi;
            if (v0 >= v1) { mv2 = v0; mi = lane; } else { mv2 = v1; mi = lane + 32; }
            for (int off = 16; off; off >>= 1) {
                float ov = __shfl_xor_sync(0xffffffffu, mv2, off);
                int   oi = __shfl_xor_sync(0xffffffffu, mi, off);
                if (ov > mv2 || (ov == mv2 && oi < mi)) { mv2 = ov; mi = oi; }
            }
            float e0 = __expf(v0 - mv2), e1 = __expf(v1 - mv2);
            float sum = e0 + e1;
            for (int off = 16; off; off >>= 1)
                sum += __shfl_xor_sync(0xffffffffu, sum, off);
            float inv = __fdividef(1.f, sum);
            int b = bid * BM + m;
            if (b < Bsz) {
                float* op = out + ((size_t)(step + 1) * Bsz + b) * Lsz;
                op[lane]      = e0 * inv;
                op[lane + 32] = e1 * inv;
            }
            if (lane == 0) idx_s[m] = mi;
        }
        __syncthreads();
    }
}

extern "C" void kernel_launch(void* const* d_in, const int* in_sizes, int n_in,
                              void* d_out, int out_size)
{
    const float* dec   = (const float*)d_in[0];
    const float* emb   = (const float*)d_in[1];
    const float* ctx   = (const float*)d_in[2];
    const float* h0    = (const float*)d_in[3];
    const float* c0    = (const float*)d_in[4];
    const float* Wih   = (const float*)d_in[5];
    const float* Whh   = (const float*)d_in[6];
    const float* bih   = (const float*)d_in[7];
    const float* bhh   = (const float*)d_in[8];
    const float* gWq   = (const float*)d_in[9];
    const float* gbq   = (const float*)d_in[10];
    const float* gWref = (const float*)d_in[11];
    const float* gbref = (const float*)d_in[12];
    const float* gv    = (const float*)d_in[13];
    const float* pWq   = (const float*)d_in[14];
    const float* pbq   = (const float*)d_in[15];
    const float* pWref = (const float*)d_in[16];
    const float* pbref = (const float*)d_in[17];
    const float* pv    = (const float*)d_in[18];
    float* out = (float*)d_out;

    cudaFuncSetAttribute(ptrnet_main, cudaFuncAttributeMaxDynamicSharedMemorySize,
                         SMEM_FLOATS * 4);

    ptrnet_prew<<<80, 512>>>(Wih, Whh, gWq, pWq);
    ptrnet_preP<<<Bsz, 512>>>(emb, dec, bih, bhh);
    ptrnet_pre<<<Bsz, 128>>>(ctx, gWref, gbref, pWref, pbref);
    ptrnet_main<<<GRID, NT, SMEM_FLOATS * 4>>>(h0, c0, gbq, pbq, gv, pv, out);
}

// round 11
// speedup vs baseline: 2.4060x; 1.0897x over previous
#include <cuda_runtime.h>
#include <math.h>

#define Bsz 2048
#define Lsz 64
#define Esz 128
#define Hsz 128
#define NSTEPS 126
#define BM 7
#define NT 512
#define GRID 293               // ceil(2048/7)
#define NEGV -1000000000.0f

// scratch (module-static device arrays: allowed)
__device__ float d_eg[(size_t)Bsz * Lsz * Hsz];   // e_g[b][l][h]
__device__ float d_ep[(size_t)Bsz * Lsz * Hsz];   // e_p[b][l][h]
__device__ float4 d_wt4[64 * 512];                // transposed LSTM weights [k4][o] (Wih 0..31, Whh 32..63)
__device__ float4 d_wq4[2 * 32 * 128];            // transposed gWq|pWq [which][k4][o]
__device__ float  d_P[(size_t)Bsz * Lsz * 512];   // P[b][l][o] = Wih·emb[l,b] + bt
__device__ float  d_P0[(size_t)Bsz * 512];        // P0[b][o]   = Wih·dec[b] + bt

// packed f32x2 FMA (Blackwell): d = a*b + c elementwise, IEEE rn per lane
#define FMA2(d, a, b, c) \
    asm("fma.rn.f32x2 %0, %1, %2, %3;" : "=l"(d) : "l"(a), "l"(b), "l"(c))

__device__ __forceinline__ unsigned long long pack2(float lo, float hi) {
    unsigned long long r;
    asm("mov.b64 %0, {%1, %2};" : "=l"(r) : "f"(lo), "f"(hi));
    return r;
}
__device__ __forceinline__ float hsum2(unsigned long long v) {
    float a, b;
    asm("mov.b64 {%0, %1}, %2;" : "=f"(a), "=f"(b) : "l"(v));
    return a + b;
}

__device__ __forceinline__ float ftanh(float x) {
    float e = __expf(2.f * x);
    return 1.f - __fdividef(2.f, e + 1.f);
}
__device__ __forceinline__ float fsigm(float x) {
    return __fdividef(1.f, 1.f + __expf(-x));
}

// ---------------------------------------------------------------------------
// Transpose LSTM weights + Wq matrices into coalesced [k][o] layouts
// ---------------------------------------------------------------------------
__global__ void __launch_bounds__(512) ptrnet_prew(
    const float* __restrict__ Wih, const float* __restrict__ Whh,
    const float* __restrict__ gWq, const float* __restrict__ pWq)
{
    int i = blockIdx.x * blockDim.x + threadIdx.x;
    if (i < 64 * 512) {
        int k4 = i >> 9, o = i & 511;
        const float* src = (k4 < 32) ? (Wih + o * 128 + (k4 << 2))
                                     : (Whh + o * 128 + ((k4 - 32) << 2));
        d_wt4[i] = *reinterpret_cast<const float4*>(src);
    } else if (i < 64 * 512 + 2 * 4096) {
        int j = i - 64 * 512;
        int which = j >> 12, r = j & 4095;
        int k4 = r >> 7, o = r & 127;
        const float* W = which ? pWq : gWq;
        d_wq4[which * 4096 + k4 * 128 + o] =
            *reinterpret_cast<const float4*>(W + o * 128 + (k4 << 2));
    }
}

// ---------------------------------------------------------------------------
// Precompute P[b][l][o] = Wih·emb[l][b] + (bih+bhh)[o]  and P0 from decoder.
// ---------------------------------------------------------------------------
__global__ void __launch_bounds__(512) ptrnet_preP(
    const float* __restrict__ emb, const float* __restrict__ dec,
    const float* __restrict__ bih, const float* __restrict__ bhh)
{
    __shared__ float xs[Lsz * Esz];   // 32KB
    __shared__ float ds[Esz];
    const int b = blockIdx.x, o = threadIdx.x;

    for (int idx = o; idx < Lsz * Esz; idx += 512) {
        int l = idx >> 7, e = idx & 127;
        xs[idx] = emb[((size_t)l * Bsz + b) * Esz + e];
    }
    if (o < Esz) ds[o] = dec[(size_t)b * Esz + o];
    __syncthreads();

    const float bt = bih[o] + bhh[o];

    {   // P0
        unsigned long long acc = pack2(bt, 0.f);
        #pragma unroll 8
        for (int kk = 0; kk < 32; kk++) {
            ulonglong2 w2 = *reinterpret_cast<const ulonglong2*>(&d_wt4[(kk << 9) + o]);
            ulonglong2 x2 = *reinterpret_cast<const ulonglong2*>(&ds[kk << 2]);
            FMA2(acc, w2.x, x2.x, acc);
            FMA2(acc, w2.y, x2.y, acc);
        }
        d_P0[(size_t)b * 512 + o] = hsum2(acc);
    }
    for (int c = 0; c < 4; c++) {
        unsigned long long acc[16];
        #pragma unroll
        for (int j = 0; j < 16; j++) acc[j] = pack2(bt, 0.f);
        #pragma unroll 2
        for (int kk = 0; kk < 32; kk++) {
            ulonglong2 w2 = *reinterpret_cast<const ulonglong2*>(&d_wt4[(kk << 9) + o]);
            #pragma unroll
            for (int j = 0; j < 16; j++) {
                ulonglong2 x2 = *reinterpret_cast<const ulonglong2*>(
                    &xs[(((c << 4) + j) << 7) + (kk << 2)]);
                FMA2(acc[j], w2.x, x2.x, acc[j]);
                FMA2(acc[j], w2.y, x2.y, acc[j]);
            }
        }
        #pragma unroll
        for (int j = 0; j < 16; j++)
            d_P[(((size_t)b << 6) + (c << 4) + j) * 512 + o] = hsum2(acc[j]);
    }
}

// ---------------------------------------------------------------------------
// Precompute e_g/e_p
// ---------------------------------------------------------------------------
__global__ void __launch_bounds__(128) ptrnet_pre(
    const float* __restrict__ ctx,
    const float* __restrict__ gWref, const float* __restrict__ gbref,
    const float* __restrict__ pWref, const float* __restrict__ pbref)
{
    __shared__ float cs[Lsz * Hsz];
    const int b = blockIdx.x, t = threadIdx.x;
    for (int l = 0; l < Lsz; l++)
        cs[l * Hsz + t] = ctx[((size_t)l * Bsz + b) * Hsz + t];
    __syncthreads();

    {
        float acc[Lsz];
        #pragma unroll
        for (int l = 0; l < Lsz; l++) acc[l] = 0.f;
        const float4* wr = reinterpret_cast<const float4*>(gWref + t * Hsz);
        #pragma unroll 1
        for (int k4 = 0; k4 < 32; k4++) {
            float4 w = wr[k4];
            #pragma unroll
            for (int l = 0; l < Lsz; l++) {
                float4 c = *reinterpret_cast<const float4*>(&cs[l * Hsz + k4 * 4]);
                acc[l] += w.x * c.x + w.y * c.y + w.z * c.z + w.w * c.w;
            }
        }
        float bias = gbref[t];
        #pragma unroll
        for (int l = 0; l < Lsz; l++)
            d_eg[((size_t)b * Lsz + l) * Hsz + t] = acc[l] + bias;
    }
    {
        float acc[Lsz];
        #pragma unroll
        for (int l = 0; l < Lsz; l++) acc[l] = 0.f;
        const float4* wr = reinterpret_cast<const float4*>(pWref + t * Hsz);
        #pragma unroll 1
        for (int k4 = 0; k4 < 32; k4++) {
            float4 w = wr[k4];
            #pragma unroll
            for (int l = 0; l < Lsz; l++) {
                float4 c = *reinterpret_cast<const float4*>(&cs[l * Hsz + k4 * 4]);
                acc[l] += w.x * c.x + w.y * c.y + w.z * c.z + w.w * c.w;
            }
        }
        float bias = pbref[t];
        #pragma unroll
        for (int l = 0; l < Lsz; l++)
            d_ep[((size_t)b * Lsz + l) * Hsz + t] = acc[l] + bias;
    }
}

// ---------------------------------------------------------------------------
// Persistent decode kernel — 512 threads, BM=7, 2 CTAs/SM for phase overlap.
// Wq read from global (L1-resident, 7x register reuse).
// smem float offsets:
// ---------------------------------------------------------------------------
#define OXH  0                     // [7][128] h                  896
#define OG   896                   // [7][512] gates / [28][128] qg-qp partials
#define OC   4480                  // [7][128]                    896
#define OQ   5376                  // [7][128]                    896
#define OGL  6272                  // [7][128]                    896
#define OU   7168                  // [7][64]                     448
#define OS   7616                  // [7][64]                     448
#define OGBQ 8064
#define OPBQ 8192
#define OGV  8320
#define OPV  8448
#define SMEM_FLOATS 8576           // 34304 bytes -> 2 CTAs/SM

__global__ void __launch_bounds__(NT, 2) ptrnet_main(
    const float* __restrict__ h0,  const float* __restrict__ c0,
    const float* __restrict__ gbq, const float* __restrict__ pbq,
    const float* __restrict__ gv,  const float* __restrict__ pv,
    float* __restrict__ out)
{
    extern __shared__ float s[];
    __shared__ unsigned long long mask_s[BM];
    __shared__ int idx_s[BM];
    __shared__ int bb_s[BM];
    __shared__ int cnt_s[BM];
    __shared__ int off_s[BM];
    __shared__ int R_s;
    __shared__ unsigned short rowlist[BM * Lsz];

    const int tid = threadIdx.x;
    const int bid = blockIdx.x;

    // ---- prologue ----
    if (tid < 128) {
        s[OGBQ + tid] = gbq[tid];  s[OPBQ + tid] = pbq[tid];
        s[OGV + tid]  = gv[tid];   s[OPV + tid]  = pv[tid];
    }
    for (int i = tid; i < BM * Hsz; i += NT) {
        int m = i >> 7, j = i & 127;
        int bb = min(bid * BM + m, Bsz - 1);
        s[OXH + m * 128 + j] = h0[bb * Hsz + j];
        s[OC  + m * 128 + j] = c0[bb * Hsz + j];
    }
    if (tid < BM) {
        mask_s[tid] = 0ull; idx_s[tid] = 0;
        bb_s[tid] = min(bid * BM + tid, Bsz - 1);
    }
    for (int i = tid; i < BM * Lsz; i += NT) {
        int m = i >> 6, l = i & 63;
        int b = bid * BM + m;
        if (b < Bsz) out[(size_t)b * Lsz + l] = (l == 0) ? 1.0f : 0.0f;
    }
    __syncthreads();

    const int warp = tid >> 5, lane = tid & 31;
    const int grp = lane >> 3, lk = lane & 7;
    const int o128 = tid & 127;
    const int kq = tid >> 7;            // 0..3 (qg/qp split-K slice)

    // hoisted attention vectors
    float4 gvr[4], pvr[4];
    #pragma unroll
    for (int j = 0; j < 4; j++) {
        gvr[j] = *reinterpret_cast<const float4*>(&s[OGV + (((j << 3) + lk) << 2)]);
        pvr[j] = *reinterpret_cast<const float4*>(&s[OPV + (((j << 3) + lk) << 2)]);
    }

    for (int step = 0; step < NSTEPS; step++) {
        // ---- preload P rows for phase B ----
        float pA0[2], pA1[2], pA2[2], pA3[2];
        #pragma unroll
        for (int it = 0; it < 2; it++) {
            int i = tid + it * NT;
            if (i < BM * Hsz) {
                int m = i >> 7, j = i & 127;
                const float* pr = (step == 0)
                    ? (d_P0 + (size_t)bb_s[m] * 512)
                    : (d_P + (((size_t)bb_s[m] << 6) + idx_s[m]) * 512);
                pA0[it] = pr[j];       pA1[it] = pr[128 + j];
                pA2[it] = pr[256 + j]; pA3[it] = pr[384 + j];
            }
        }

        // ---- mask update ----
        if (tid < BM) {
            unsigned long long mk = mask_s[tid] | (1ull << idx_s[tid]);
            if (idx_s[tid] != 0) mk &= ~1ull;
            mask_s[tid] = mk;
            cnt_s[tid] = 64 - __popcll(mk);
        }

        // ---- phase A: Whh·h, full K per thread (o = tid) ----
        {
            unsigned long long acc[BM];
            #pragma unroll
            for (int m = 0; m < BM; m++) acc[m] = pack2(0.f, 0.f);
            #pragma unroll 8
            for (int kk = 0; kk < 32; kk++) {
                const ulonglong2 w2 = *reinterpret_cast<const ulonglong2*>(
                    &d_wt4[((32 + kk) << 9) + tid]);
                #pragma unroll
                for (int m = 0; m < BM; m++) {
                    const ulonglong2 x2 = *reinterpret_cast<const ulonglong2*>(
                        &s[OXH + m * 128 + (kk << 2)]);
                    FMA2(acc[m], w2.x, x2.x, acc[m]);
                    FMA2(acc[m], w2.y, x2.y, acc[m]);
                }
            }
            #pragma unroll
            for (int m = 0; m < BM; m++) s[OG + m * 512 + tid] = hsum2(acc[m]);
        }
        __syncthreads();

        // ---- phase B: gates + P; LSTM pointwise; rowlist ----
        #pragma unroll
        for (int it = 0; it < 2; it++) {
            int i = tid + it * NT;
            if (i < BM * Hsz) {
                int m = i >> 7, j = i & 127;
                float ig = fsigm(s[OG + m * 512 + j]       + pA0[it]);
                float fg = fsigm(s[OG + m * 512 + 128 + j] + pA1[it]);
                float gg = ftanh(s[OG + m * 512 + 256 + j] + pA2[it]);
                float og = fsigm(s[OG + m * 512 + 384 + j] + pA3[it]);
                float cn = fg * s[OC + m * 128 + j] + ig * gg;
                s[OC + m * 128 + j] = cn;
                s[OXH + m * 128 + j] = og * ftanh(cn);
            }
        }
        if (tid < BM) {
            int off = 0;
            for (int j = 0; j < tid; j++) off += cnt_s[j];
            off_s[tid] = off;
            unsigned long long unm = ~mask_s[tid];
            int k = 0;
            while (unm) {
                int l = __ffsll((long long)unm) - 1;
                rowlist[off + k] = (unsigned short)((tid << 6) | l);
                k++;
                unm &= unm - 1;
            }
        }
        if (tid == 0) {
            int R = 0;
            #pragma unroll
            for (int j = 0; j < BM; j++) R += cnt_s[j];
            R_s = R;
        }
        __syncthreads();

        const int Rv = R_s;
        const int nIter = (Rv + 63) >> 6;   // 16 warps x 4 groups = 64 rows/sweep

        // ---- terminal state: burst uniform 1/64 + exit ----
        if (Rv == 0) {
            const float u = 0.015625f;
            for (int st = step + 1; st <= NSTEPS; st++) {
                float* orow = out + (size_t)st * Bsz * Lsz;
                for (int i = tid; i < BM * Lsz; i += NT) {
                    int m = i >> 6;
                    int b = bid * BM + m;
                    if (b < Bsz) orow[(size_t)b * Lsz + (i & 63)] = u;
                }
            }
            return;
        }

        // ---- qg partials: thread (kq, o128) does 7 m over 8 k4; Wq from global ----
        {
            unsigned long long acc[BM];
            #pragma unroll
            for (int j = 0; j < BM; j++) acc[j] = pack2(0.f, 0.f);
            #pragma unroll
            for (int kk = 0; kk < 8; kk++) {
                const int k4 = (kq << 3) + kk;
                ulonglong2 w2 = *reinterpret_cast<const ulonglong2*>(
                    &d_wq4[(k4 << 7) + o128]);
                #pragma unroll
                for (int j = 0; j < BM; j++) {
                    ulonglong2 h2 = *reinterpret_cast<const ulonglong2*>(
                        &s[OXH + j * 128 + (k4 << 2)]);
                    FMA2(acc[j], w2.x, h2.x, acc[j]);
                    FMA2(acc[j], w2.y, h2.y, acc[j]);
                }
            }
            #pragma unroll
            for (int j = 0; j < BM; j++)
                s[OG + ((kq * BM + j) << 7) + o128] = hsum2(acc[j]);
        }
        __syncthreads();

        // ---- qg reduce (strided: BM*128 = 896 > NT) ----
        for (int i = tid; i < BM * 128; i += NT) {
            int m = i >> 7, o = i & 127;
            float q = ((s[OG + ((m) << 7) + o]           + s[OG + ((BM + m) << 7) + o])
                     + (s[OG + ((2 * BM + m) << 7) + o]  + s[OG + ((3 * BM + m) << 7) + o]))
                     + s[OGBQ + o];
            s[OQ + (m << 7) + o] = q;
        }
        __syncthreads();

        // ---- ug: only unmasked rows ----
        for (int k = 0; k < nIter; k++) {
            int r = warp * 4 + grp + (k << 6);
            bool valid = (r < Rv);
            int e = rowlist[valid ? r : 0];
            int m = e >> 6, l = e & 63;
            const float4* e4 = reinterpret_cast<const float4*>(
                d_eg + ((size_t)bb_s[m] * Lsz + l) * Hsz);
            float acc = 0.f;
            #pragma unroll
            for (int j = 0; j < 4; j++) {
                int k4 = (j << 3) + lk;
                float4 ev = e4[k4];
                float4 q = *reinterpret_cast<const float4*>(&s[OQ + m * 128 + (k4 << 2)]);
                float4 g = gvr[j];
                acc += g.x * ftanh(q.x + ev.x) + g.y * ftanh(q.y + ev.y)
                     + g.z * ftanh(q.z + ev.z) + g.w * ftanh(q.w + ev.w);
            }
            acc += __shfl_xor_sync(0xffffffffu, acc, 1);
            acc += __shfl_xor_sync(0xffffffffu, acc, 2);
            acc += __shfl_xor_sync(0xffffffffu, acc, 4);
            if (valid && lk == 0) s[OU + (m << 6) + l] = acc;
        }
        __syncthreads();

        // ---- glimpse softmax (masked) ----
        if (warp < BM) {
            int m = warp;
            unsigned long long mk = mask_s[m];
            float v0 = ((mk >> lane) & 1ull)        ? NEGV : s[OU + m * 64 + lane];
            float v1 = ((mk >> (lane + 32)) & 1ull) ? NEGV : s[OU + m * 64 + 32 + lane];
            float mx = fmaxf(v0, v1);
            for (int off = 16; off; off >>= 1)
                mx = fmaxf(mx, __shfl_xor_sync(0xffffffffu, mx, off));
            float e0 = __expf(v0 - mx), e1 = __expf(v1 - mx);
            float sum = e0 + e1;
            for (int off = 16; off; off >>= 1)
                sum += __shfl_xor_sync(0xffffffffu, sum, off);
            float inv = __fdividef(1.f, sum);
            s[OS + m * 64 + lane]      = e0 * inv;
            s[OS + m * 64 + 32 + lane] = e1 * inv;
        }
        __syncthreads();

        // ---- g_l[m][h] = sum_l e_g[b][l][h] * sm[m][l] (skip sm==0) ----
        {
            const int mg4 = tid >> 7;
            for (int m = mg4; m < BM; m += 4) {
                const float* eg = d_eg + ((size_t)bb_s[m] * Lsz) * Hsz + o128;
                float acc = 0.f;
                int off = off_s[m], cn = cnt_s[m];
                for (int j = 0; j < cn; j++) {
                    int l = rowlist[off + j] & 63;
                    acc += eg[(size_t)l * Hsz] * s[OS + m * 64 + l];
                }
                s[OGL + m * 128 + o128] = acc;
            }
        }
        __syncthreads();

        // ---- qp partials ----
        {
            unsigned long long acc[BM];
            #pragma unroll
            for (int j = 0; j < BM; j++) acc[j] = pack2(0.f, 0.f);
            #pragma unroll
            for (int kk = 0; kk < 8; kk++) {
                const int k4 = (kq << 3) + kk;
                ulonglong2 w2 = *reinterpret_cast<const ulonglong2*>(
                    &d_wq4[4096 + (k4 << 7) + o128]);
                #pragma unroll
                for (int j = 0; j < BM; j++) {
                    ulonglong2 g2 = *reinterpret_cast<const ulonglong2*>(
                        &s[OGL + j * 128 + (k4 << 2)]);
                    FMA2(acc[j], w2.x, g2.x, acc[j]);
                    FMA2(acc[j], w2.y, g2.y, acc[j]);
                }
            }
            #pragma unroll
            for (int j = 0; j < BM; j++)
                s[OG + ((kq * BM + j) << 7) + o128] = hsum2(acc[j]);
        }
        __syncthreads();

        // ---- qp reduce (strided: BM*128 = 896 > NT) ----
        for (int i = tid; i < BM * 128; i += NT) {
            int m = i >> 7, o = i & 127;
            float q = ((s[OG + ((m) << 7) + o]           + s[OG + ((BM + m) << 7) + o])
                     + (s[OG + ((2 * BM + m) << 7) + o]  + s[OG + ((3 * BM + m) << 7) + o]))
                     + s[OPBQ + o];
            s[OQ + (m << 7) + o] = q;
        }
        __syncthreads();

        // ---- up: only unmasked rows ----
        for (int k = 0; k < nIter; k++) {
            int r = warp * 4 + grp + (k << 6);
            bool valid = (r < Rv);
            int e = rowlist[valid ? r : 0];
            int m = e >> 6, l = e & 63;
            const float4* e4 = reinterpret_cast<const float4*>(
                d_ep + ((size_t)bb_s[m] * Lsz + l) * Hsz);
            float acc = 0.f;
            #pragma unroll
            for (int j = 0; j < 4; j++) {
                int k4 = (j << 3) + lk;
                float4 ev = e4[k4];
                float4 q = *reinterpret_cast<const float4*>(&s[OQ + m * 128 + (k4 << 2)]);
                float4 p = pvr[j];
                acc += p.x * ftanh(q.x + ev.x) + p.y * ftanh(q.y + ev.y)
                     + p.z * ftanh(q.z + ev.z) + p.w * ftanh(q.w + ev.w);
            }
            acc += __shfl_xor_sync(0xffffffffu, acc, 1);
            acc += __shfl_xor_sync(0xffffffffu, acc, 2);
            acc += __shfl_xor_sync(0xffffffffu, acc, 4);
            if (valid && lk == 0) s[OU + (m << 6) + l] = acc;
        }
        __syncthreads();

        // ---- pointer: 10*tanh, mask, softmax, argmax, write probs ----
        if (warp < BM) {
            int m = warp;
            unsigned long long mk = mask_s[m];
            float r0 = 10.f * tanhf(s[OU + m * 64 + lane]);
            float r1 = 10.f * tanhf(s[OU + m * 64 + 32 + lane]);
            float v0 = ((mk >> lane) & 1ull)        ? NEGV : r0;
            float v1 = ((mk >> (lane + 32)) & 1ull) ? NEGV : r1;
            float mv2; int mi;
            if (v0 >= v1) { mv2 = v0; mi = lane; } else { mv2 = v1; mi = lane + 32; }
            for (int off = 16; off; off >>= 1) {
                float ov = __shfl_xor_sync(0xffffffffu, mv2, off);
                int   oi = __shfl_xor_sync(0xffffffffu, mi, off);
                if (ov > mv2 || (ov == mv2 && oi < mi)) { mv2 = ov; mi = oi; }
            }
            float e0 = __expf(v0 - mv2), e1 = __expf(v1 - mv2);
            float sum = e0 + e1;
            for (int off = 16; off; off >>= 1)
                sum += __shfl_xor_sync(0xffffffffu, sum, off);
            float inv = __fdividef(1.f, sum);
            int b = bid * BM + m;
            if (b < Bsz) {
                float* op = out + ((size_t)(step + 1) * Bsz + b) * Lsz;
                op[lane]      = e0 * inv;
                op[lane + 32] = e1 * inv;
            }
            if (lane == 0) idx_s[m] = mi;
        }
        __syncthreads();
    }
}

extern "C" void kernel_launch(void* const* d_in, const int* in_sizes, int n_in,
                              void* d_out, int out_size)
{
    const float* dec   = (const float*)d_in[0];
    const float* emb   = (const float*)d_in[1];
    const float* ctx   = (const float*)d_in[2];
    const float* h0    = (const float*)d_in[3];
    const float* c0    = (const float*)d_in[4];
    const float* Wih   = (const float*)d_in[5];
    const float* Whh   = (const float*)d_in[6];
    const float* bih   = (const float*)d_in[7];
    const float* bhh   = (const float*)d_in[8];
    const float* gWq   = (const float*)d_in[9];
    const float* gbq   = (const float*)d_in[10];
    const float* gWref = (const float*)d_in[11];
    const float* gbref = (const float*)d_in[12];
    const float* gv    = (const float*)d_in[13];
    const float* pWq   = (const float*)d_in[14];
    const float* pbq   = (const float*)d_in[15];
    const float* pWref = (const float*)d_in[16];
    const float* pbref = (const float*)d_in[17];
    const float* pv    = (const float*)d_in[18];
    float* out = (float*)d_out;

    cudaFuncSetAttribute(ptrnet_main, cudaFuncAttributeMaxDynamicSharedMemorySize,
                         SMEM_FLOATS * 4);

    ptrnet_prew<<<80, 512>>>(Wih, Whh, gWq, pWq);
    ptrnet_preP<<<Bsz, 512>>>(emb, dec, bih, bhh);
    ptrnet_pre<<<Bsz, 128>>>(ctx, gWref, gbref, pWref, pbref);
    ptrnet_main<<<GRID, NT, SMEM_FLOATS * 4>>>(h0, c0, gbq, pbq, gv, pv, out);
}